// round 2
// baseline (speedup 1.0000x reference)
#include <cuda_runtime.h>
#include <cuda_bf16.h>
#include <math.h>

#define N_NODES 50000
#define D_MODEL 128
#define H_HEADS 8
#define DH 16
#define DFF 512
#define E_EDGES 800000
#define TOT_EDGES (E_EDGES + N_NODES)   // self loops appended
#define LN_EPS 1e-6f
#define NEG_SLOPE 0.2f

// ---------------- scratch (no allocations allowed) ----------------
__device__ __align__(16) float    g_x[(size_t)N_NODES * D_MODEL];   // projected features [N,128]
__device__ __align__(16) float    g_as[N_NODES * H_HEADS];          // alpha_src logits
__device__ __align__(16) float    g_ad[N_NODES * H_HEADS];          // alpha_dst logits
__device__ __align__(16) unsigned g_m[N_NODES * H_HEADS];           // segment max (ordered-uint float)
__device__ __align__(16) float    g_den[N_NODES * H_HEADS];         // softmax denominators

// ordered-uint encoding of float (monotonic under unsigned compare)
__device__ __forceinline__ unsigned f2ord(float f) {
    unsigned b = __float_as_uint(f);
    return (b & 0x80000000u) ? ~b : (b | 0x80000000u);
}
__device__ __forceinline__ float ord2f(unsigned k) {
    unsigned b = (k & 0x80000000u) ? (k & 0x7fffffffu) : ~k;
    return __uint_as_float(b);
}
__device__ __forceinline__ float leaky(float x) { return x > 0.f ? x : NEG_SLOPE * x; }

// ---------------- K0: out = nf + bias_att ; init m/den -----------
__global__ void __launch_bounds__(256) k0_init(const float* __restrict__ nf,
                                               const float* __restrict__ bias_att,
                                               float* __restrict__ out) {
    int i = blockIdx.x * 256 + threadIdx.x;               // over N*D/4 float4s
    const int tot4 = N_NODES * D_MODEL / 4;
    if (i < tot4) {
        float4 v = ((const float4*)nf)[i];
        float4 b = ((const float4*)bias_att)[i & 31];
        v.x += b.x; v.y += b.y; v.z += b.z; v.w += b.w;
        ((float4*)out)[i] = v;
    }
    if (i < N_NODES * H_HEADS) { g_m[i] = 0u; g_den[i] = 0.f; }
}

// ---------------- K1: LN1 -> x = h1 @ W_att ; a_s, a_d -----------
// block = 128 threads, 16 rows per block (3125 blocks exactly)
__global__ void __launch_bounds__(128) k1_ln_proj(const float* __restrict__ nf,
                                                  const float* __restrict__ g1,
                                                  const float* __restrict__ b1,
                                                  const float* __restrict__ W,
                                                  const float* __restrict__ asrc,
                                                  const float* __restrict__ adst) {
    __shared__ float h1[16][132];
    const int t = threadIdx.x;
    const int blk = blockIdx.x;

    // Phase A: layernorm (8 threads per row, 16 elems per thread)
    {
        int r = t >> 3, p = t & 7;
        int row = blk * 16 + r;
        const float4* rp = (const float4*)(nf + (size_t)row * D_MODEL + p * 16);
        float v[16];
#pragma unroll
        for (int j = 0; j < 4; j++) {
            float4 q = rp[j];
            v[4 * j] = q.x; v[4 * j + 1] = q.y; v[4 * j + 2] = q.z; v[4 * j + 3] = q.w;
        }
        float s = 0.f, s2 = 0.f;
#pragma unroll
        for (int j = 0; j < 16; j++) { s += v[j]; s2 += v[j] * v[j]; }
#pragma unroll
        for (int o = 4; o; o >>= 1) {
            s  += __shfl_xor_sync(0xffffffffu, s, o);
            s2 += __shfl_xor_sync(0xffffffffu, s2, o);
        }
        float mean = s * (1.f / 128.f);
        float var = (s2 * (1.f / 128.f) - mean * mean) * (128.f / 127.f);
        float rstd = 1.f / (sqrtf(fmaxf(var, 0.f)) + LN_EPS);
#pragma unroll
        for (int j = 0; j < 16; j++) {
            int c = p * 16 + j;
            h1[r][c] = g1[c] * (v[j] - mean) * rstd + b1[c];
        }
    }
    __syncthreads();

    // Phase B: 16x128 tile GEMM, thread tile 4 rows x 4 cols
    const int r0 = (t >> 5) << 2;     // warp owns 4 rows
    const int cg = t & 31;
    const int c0 = cg << 2;           // 4 consecutive cols
    float acc[4][4] = {};
#pragma unroll 4
    for (int k = 0; k < 128; k++) {
        float4 w = *(const float4*)(W + k * D_MODEL + c0);
#pragma unroll
        for (int i = 0; i < 4; i++) {
            float a = h1[r0 + i][k];
            acc[i][0] += a * w.x; acc[i][1] += a * w.y;
            acc[i][2] += a * w.z; acc[i][3] += a * w.w;
        }
    }

    // Phase C: write x + attention logits
    const int hh = cg >> 2, sub = cg & 3;
#pragma unroll
    for (int i = 0; i < 4; i++) {
        int rr = blk * 16 + r0 + i;
        *(float4*)(g_x + (size_t)rr * D_MODEL + c0) =
            make_float4(acc[i][0], acc[i][1], acc[i][2], acc[i][3]);
        float ps = 0.f, pd = 0.f;
#pragma unroll
        for (int j = 0; j < 4; j++) {
            float av = acc[i][j];
            ps += av * asrc[hh * DH + sub * 4 + j];
            pd += av * adst[hh * DH + sub * 4 + j];
        }
        ps += __shfl_xor_sync(0xffffffffu, ps, 1);
        ps += __shfl_xor_sync(0xffffffffu, ps, 2);
        pd += __shfl_xor_sync(0xffffffffu, pd, 1);
        pd += __shfl_xor_sync(0xffffffffu, pd, 2);
        if (sub == 0) { g_as[rr * H_HEADS + hh] = ps; g_ad[rr * H_HEADS + hh] = pd; }
    }
}

// ---------------- K2: segment max over edges ----------------------
__global__ void __launch_bounds__(256) k2_max(const int* __restrict__ ei) {
    int e = blockIdx.x * 256 + threadIdx.x;
    if (e >= TOT_EDGES) return;
    int src, dst;
    if (e < E_EDGES) { src = __ldg(ei + e); dst = __ldg(ei + E_EDGES + e); }
    else             { src = dst = e - E_EDGES; }
    float4 s0 = *(const float4*)(g_as + src * 8);
    float4 s1 = *(const float4*)(g_as + src * 8 + 4);
    float4 d0 = *(const float4*)(g_ad + dst * 8);
    float4 d1 = *(const float4*)(g_ad + dst * 8 + 4);
    float ev[8] = { s0.x + d0.x, s0.y + d0.y, s0.z + d0.z, s0.w + d0.w,
                    s1.x + d1.x, s1.y + d1.y, s1.z + d1.z, s1.w + d1.w };
#pragma unroll
    for (int h = 0; h < 8; h++)
        atomicMax(&g_m[dst * 8 + h], f2ord(leaky(ev[h])));
}

// ---------------- K3: softmax denominators ------------------------
__global__ void __launch_bounds__(256) k3_den(const int* __restrict__ ei) {
    int e = blockIdx.x * 256 + threadIdx.x;
    if (e >= TOT_EDGES) return;
    int src, dst;
    if (e < E_EDGES) { src = __ldg(ei + e); dst = __ldg(ei + E_EDGES + e); }
    else             { src = dst = e - E_EDGES; }
    float4 s0 = *(const float4*)(g_as + src * 8);
    float4 s1 = *(const float4*)(g_as + src * 8 + 4);
    float4 d0 = *(const float4*)(g_ad + dst * 8);
    float4 d1 = *(const float4*)(g_ad + dst * 8 + 4);
    float ev[8] = { s0.x + d0.x, s0.y + d0.y, s0.z + d0.z, s0.w + d0.w,
                    s1.x + d1.x, s1.y + d1.y, s1.z + d1.z, s1.w + d1.w };
#pragma unroll
    for (int h = 0; h < 8; h++) {
        float m = ord2f(g_m[dst * 8 + h]);
        atomicAdd(&g_den[dst * 8 + h], expf(leaky(ev[h]) - m));
    }
}

// ---------------- K4: weighted scatter (warp per edge) ------------
__global__ void __launch_bounds__(256) k4_scatter(const int* __restrict__ ei,
                                                  float* __restrict__ out) {
    int gt = blockIdx.x * 256 + threadIdx.x;
    int w = gt >> 5, l = gt & 31;
    if (w >= TOT_EDGES) return;
    int src, dst;
    if (w < E_EDGES) { src = __ldg(ei + w); dst = __ldg(ei + E_EDGES + w); }
    else             { src = dst = w - E_EDGES; }
    int h = l >> 2;
    float e = __ldg(g_as + src * 8 + h) + __ldg(g_ad + dst * 8 + h);
    e = leaky(e);
    float m = ord2f(g_m[dst * 8 + h]);
    float den = g_den[dst * 8 + h];
    float alpha = expf(e - m) / (den + 1e-16f);
    float4 xv = *(const float4*)(g_x + (size_t)src * D_MODEL + l * 4);
    float4 mv = make_float4(xv.x * alpha, xv.y * alpha, xv.z * alpha, xv.w * alpha);
    atomicAdd((float4*)(out + (size_t)dst * D_MODEL + l * 4), mv);
}

// ---------------- K5: fused LN2 + FFN + residual -------------------
// block = 256 threads, 16 rows per block (3125 blocks)
__global__ void __launch_bounds__(256) k5_ffn(float* __restrict__ out,
                                              const float* __restrict__ g2,
                                              const float* __restrict__ b2v,
                                              const float* __restrict__ W1,
                                              const float* __restrict__ bb1,
                                              const float* __restrict__ W2,
                                              const float* __restrict__ bb2) {
    __shared__ float h2[16][132];
    __shared__ float act[16][520];
    const int t = threadIdx.x;
    const int blk = blockIdx.x;

    // Phase A: LN2 (16 threads per row, 8 elems each)
    {
        int r = t >> 4, p = t & 15;
        int row = blk * 16 + r;
        const float4* rp = (const float4*)(out + (size_t)row * D_MODEL + p * 8);
        float4 q0 = rp[0], q1 = rp[1];
        float v[8] = { q0.x, q0.y, q0.z, q0.w, q1.x, q1.y, q1.z, q1.w };
        float s = 0.f, s2 = 0.f;
#pragma unroll
        for (int j = 0; j < 8; j++) { s += v[j]; s2 += v[j] * v[j]; }
#pragma unroll
        for (int o = 8; o; o >>= 1) {
            s  += __shfl_xor_sync(0xffffffffu, s, o);
            s2 += __shfl_xor_sync(0xffffffffu, s2, o);
        }
        float mean = s * (1.f / 128.f);
        float var = (s2 * (1.f / 128.f) - mean * mean) * (128.f / 127.f);
        float rstd = 1.f / (sqrtf(fmaxf(var, 0.f)) + LN_EPS);
#pragma unroll
        for (int j = 0; j < 8; j++) {
            int c = p * 8 + j;
            h2[r][c] = g2[c] * (v[j] - mean) * rstd + b2v[c];
        }
    }
    __syncthreads();

    const int r0 = (t >> 6) << 2;        // 4 row groups of 4
    // Phase B: GEMM1 (128 -> 512) + bias + relu, thread tile 4x8
    {
        const int c0 = (t & 63) << 3;
        float a1[4][8] = {};
#pragma unroll 2
        for (int k = 0; k < 128; k++) {
            float4 w0 = *(const float4*)(W1 + k * DFF + c0);
            float4 w1 = *(const float4*)(W1 + k * DFF + c0 + 4);
#pragma unroll
            for (int i = 0; i < 4; i++) {
                float a = h2[r0 + i][k];
                a1[i][0] += a * w0.x; a1[i][1] += a * w0.y;
                a1[i][2] += a * w0.z; a1[i][3] += a * w0.w;
                a1[i][4] += a * w1.x; a1[i][5] += a * w1.y;
                a1[i][6] += a * w1.z; a1[i][7] += a * w1.w;
            }
        }
        float4 bv0 = *(const float4*)(bb1 + c0);
        float4 bv1 = *(const float4*)(bb1 + c0 + 4);
        float bb[8] = { bv0.x, bv0.y, bv0.z, bv0.w, bv1.x, bv1.y, bv1.z, bv1.w };
#pragma unroll
        for (int i = 0; i < 4; i++)
#pragma unroll
            for (int j = 0; j < 8; j++)
                act[r0 + i][c0 + j] = fmaxf(a1[i][j] + bb[j], 0.f);
    }
    __syncthreads();

    // Phase C: GEMM2 (512 -> 128) + residual, thread tile 4x2
    {
        const int c2 = (t & 63) << 1;
        float a2[4][2] = {};
#pragma unroll 4
        for (int k = 0; k < 512; k++) {
            float2 w = *(const float2*)(W2 + k * D_MODEL + c2);
#pragma unroll
            for (int i = 0; i < 4; i++) {
                float a = act[r0 + i][k];
                a2[i][0] += a * w.x; a2[i][1] += a * w.y;
            }
        }
        float2 bb = *(const float2*)(bb2 + c2);
#pragma unroll
        for (int i = 0; i < 4; i++) {
            int rr = blk * 16 + r0 + i;
            float2 base = *(const float2*)(out + (size_t)rr * D_MODEL + c2);
            base.x += a2[i][0] + bb.x;
            base.y += a2[i][1] + bb.y;
            *(float2*)(out + (size_t)rr * D_MODEL + c2) = base;
        }
    }
}

// ---------------- host launcher -----------------------------------
extern "C" void kernel_launch(void* const* d_in, const int* in_sizes, int n_in,
                              void* d_out, int out_size) {
    const float* nf       = (const float*)d_in[0];
    const int*   ei       = (const int*)d_in[1];     // JAX demotes int64 -> int32
    const float* ln1_g    = (const float*)d_in[2];
    const float* ln1_b    = (const float*)d_in[3];
    const float* W_att    = (const float*)d_in[4];
    const float* att_src  = (const float*)d_in[5];
    const float* att_dst  = (const float*)d_in[6];
    const float* bias_att = (const float*)d_in[7];
    const float* ln2_g    = (const float*)d_in[8];
    const float* ln2_b    = (const float*)d_in[9];
    const float* W1       = (const float*)d_in[10];
    const float* b1       = (const float*)d_in[11];
    const float* W2       = (const float*)d_in[12];
    const float* b2       = (const float*)d_in[13];
    float* out = (float*)d_out;

    // K0: residual init + atomic buffers
    k0_init<<<(N_NODES * D_MODEL / 4 + 255) / 256, 256>>>(nf, bias_att, out);
    // K1: LN1 + projection + attention logits
    k1_ln_proj<<<N_NODES / 16, 128>>>(nf, ln1_g, ln1_b, W_att, att_src, att_dst);
    // K2/K3: segment softmax stats
    k2_max<<<(TOT_EDGES + 255) / 256, 256>>>(ei);
    k3_den<<<(TOT_EDGES + 255) / 256, 256>>>(ei);
    // K4: weighted message scatter (one warp per edge)
    k4_scatter<<<((size_t)TOT_EDGES * 32 + 255) / 256, 256>>>(ei, out);
    // K5: fused LN2 + FFN + residual
    k5_ffn<<<N_NODES / 16, 256>>>(out, ln2_g, ln2_b, W1, b1, W2, b2);
}

// round 3
// speedup vs baseline: 1.9495x; 1.9495x over previous
#include <cuda_runtime.h>
#include <cuda_bf16.h>
#include <math.h>

#define N_NODES 50000
#define D_MODEL 128
#define H_HEADS 8
#define DH 16
#define DFF 512
#define E_EDGES 800000
#define TOT_EDGES (E_EDGES + N_NODES)   // self loops appended
#define LN_EPS 1e-6f
#define NEG_SLOPE 0.2f

// ---------------- scratch (no allocations allowed) ----------------
__device__ __align__(16) float g_x[(size_t)N_NODES * D_MODEL];   // projected features [N,128]
__device__ __align__(16) float g_as[N_NODES * H_HEADS];          // alpha_src logits
__device__ __align__(16) float g_ad[N_NODES * H_HEADS];          // alpha_dst logits
__device__ __align__(16) float g_den[N_NODES * H_HEADS];         // softmax denominators
// bf16 split-precision weights, packed 2 consecutive k per word
__device__ __align__(16) unsigned g_w1h[64 * DFF];               // W1 hi  [kpair][n]
__device__ __align__(16) unsigned g_w1l[64 * DFF];               // W1 lo
__device__ __align__(16) unsigned g_w2h[256 * D_MODEL];          // W2 hi  [kpair][n]
__device__ __align__(16) unsigned g_w2l[256 * D_MODEL];          // W2 lo

__device__ __forceinline__ float leaky(float x) { return x > 0.f ? x : NEG_SLOPE * x; }

// split x0,x1 into packed bf16x2 hi and lo words (low half = x0)
__device__ __forceinline__ void split_pack(float x0, float x1, unsigned& hi, unsigned& lo) {
    __nv_bfloat162 h = __floats2bfloat162_rn(x0, x1);
    float2 hf = __bfloat1622float2(h);
    __nv_bfloat162 l = __floats2bfloat162_rn(x0 - hf.x, x1 - hf.y);
    hi = *reinterpret_cast<unsigned*>(&h);
    lo = *reinterpret_cast<unsigned*>(&l);
}

// D += A(16x16) * B(16x8), bf16 inputs, fp32 accum
__device__ __forceinline__ void mma16816(float* c, const unsigned* a, unsigned b0, unsigned b1) {
    asm volatile(
        "mma.sync.aligned.m16n8k16.row.col.f32.bf16.bf16.f32 "
        "{%0,%1,%2,%3}, {%4,%5,%6,%7}, {%8,%9}, {%0,%1,%2,%3};"
        : "+f"(c[0]), "+f"(c[1]), "+f"(c[2]), "+f"(c[3])
        : "r"(a[0]), "r"(a[1]), "r"(a[2]), "r"(a[3]), "r"(b0), "r"(b1));
}

// ---------------- Kprep: split W1/W2 into bf16 hi/lo, k-pair packed ----
__global__ void __launch_bounds__(256) kprep(const float* __restrict__ W1,
                                             const float* __restrict__ W2) {
    int i = blockIdx.x * 256 + threadIdx.x;
    if (i < 64 * DFF) {
        int kh = i / DFF, n = i % DFF;
        split_pack(W1[(2 * kh) * DFF + n], W1[(2 * kh + 1) * DFF + n], g_w1h[i], g_w1l[i]);
    } else {
        int j = i - 64 * DFF;   // < 256*128
        int kh = j / D_MODEL, n = j % D_MODEL;
        split_pack(W2[(2 * kh) * D_MODEL + n], W2[(2 * kh + 1) * D_MODEL + n], g_w2h[j], g_w2l[j]);
    }
}

// ---------------- K0: out = nf + bias_att ; init den ---------------
__global__ void __launch_bounds__(256) k0_init(const float* __restrict__ nf,
                                               const float* __restrict__ bias_att,
                                               float* __restrict__ out) {
    int i = blockIdx.x * 256 + threadIdx.x;               // over N*D/4 float4s
    const int tot4 = N_NODES * D_MODEL / 4;
    if (i < tot4) {
        float4 v = ((const float4*)nf)[i];
        float4 b = ((const float4*)bias_att)[i & 31];
        v.x += b.x; v.y += b.y; v.z += b.z; v.w += b.w;
        ((float4*)out)[i] = v;
    }
    if (i < N_NODES * H_HEADS) g_den[i] = 0.f;
}

// ---------------- K1: LN1 -> x = h1 @ W_att ; a_s, a_d -----------
__global__ void __launch_bounds__(128) k1_ln_proj(const float* __restrict__ nf,
                                                  const float* __restrict__ g1,
                                                  const float* __restrict__ b1,
                                                  const float* __restrict__ W,
                                                  const float* __restrict__ asrc,
                                                  const float* __restrict__ adst) {
    __shared__ float h1[16][132];
    const int t = threadIdx.x;
    const int blk = blockIdx.x;

    {
        int r = t >> 3, p = t & 7;
        int row = blk * 16 + r;
        const float4* rp = (const float4*)(nf + (size_t)row * D_MODEL + p * 16);
        float v[16];
#pragma unroll
        for (int j = 0; j < 4; j++) {
            float4 q = rp[j];
            v[4 * j] = q.x; v[4 * j + 1] = q.y; v[4 * j + 2] = q.z; v[4 * j + 3] = q.w;
        }
        float s = 0.f, s2 = 0.f;
#pragma unroll
        for (int j = 0; j < 16; j++) { s += v[j]; s2 += v[j] * v[j]; }
#pragma unroll
        for (int o = 4; o; o >>= 1) {
            s  += __shfl_xor_sync(0xffffffffu, s, o);
            s2 += __shfl_xor_sync(0xffffffffu, s2, o);
        }
        float mean = s * (1.f / 128.f);
        float var = (s2 * (1.f / 128.f) - mean * mean) * (128.f / 127.f);
        float rstd = 1.f / (sqrtf(fmaxf(var, 0.f)) + LN_EPS);
#pragma unroll
        for (int j = 0; j < 16; j++) {
            int c = p * 16 + j;
            h1[r][c] = g1[c] * (v[j] - mean) * rstd + b1[c];
        }
    }
    __syncthreads();

    const int r0 = (t >> 5) << 2;
    const int cg = t & 31;
    const int c0 = cg << 2;
    float acc[4][4] = {};
#pragma unroll 4
    for (int k = 0; k < 128; k++) {
        float4 w = *(const float4*)(W + k * D_MODEL + c0);
#pragma unroll
        for (int i = 0; i < 4; i++) {
            float a = h1[r0 + i][k];
            acc[i][0] += a * w.x; acc[i][1] += a * w.y;
            acc[i][2] += a * w.z; acc[i][3] += a * w.w;
        }
    }

    const int hh = cg >> 2, sub = cg & 3;
#pragma unroll
    for (int i = 0; i < 4; i++) {
        int rr = blk * 16 + r0 + i;
        *(float4*)(g_x + (size_t)rr * D_MODEL + c0) =
            make_float4(acc[i][0], acc[i][1], acc[i][2], acc[i][3]);
        float ps = 0.f, pd = 0.f;
#pragma unroll
        for (int j = 0; j < 4; j++) {
            float av = acc[i][j];
            ps += av * asrc[hh * DH + sub * 4 + j];
            pd += av * adst[hh * DH + sub * 4 + j];
        }
        ps += __shfl_xor_sync(0xffffffffu, ps, 1);
        ps += __shfl_xor_sync(0xffffffffu, ps, 2);
        pd += __shfl_xor_sync(0xffffffffu, pd, 1);
        pd += __shfl_xor_sync(0xffffffffu, pd, 2);
        if (sub == 0) { g_as[rr * H_HEADS + hh] = ps; g_ad[rr * H_HEADS + hh] = pd; }
    }
}

// ---------------- K3: softmax denominators (no max shift) ----------
__global__ void __launch_bounds__(256) k3_den(const int* __restrict__ ei) {
    int e = blockIdx.x * 256 + threadIdx.x;
    if (e >= TOT_EDGES) return;
    int src, dst;
    if (e < E_EDGES) { src = __ldg(ei + e); dst = __ldg(ei + E_EDGES + e); }
    else             { src = dst = e - E_EDGES; }
    float4 s0 = *(const float4*)(g_as + src * 8);
    float4 s1 = *(const float4*)(g_as + src * 8 + 4);
    float4 d0 = *(const float4*)(g_ad + dst * 8);
    float4 d1 = *(const float4*)(g_ad + dst * 8 + 4);
    float4 v0 = make_float4(expf(leaky(s0.x + d0.x)), expf(leaky(s0.y + d0.y)),
                            expf(leaky(s0.z + d0.z)), expf(leaky(s0.w + d0.w)));
    float4 v1 = make_float4(expf(leaky(s1.x + d1.x)), expf(leaky(s1.y + d1.y)),
                            expf(leaky(s1.z + d1.z)), expf(leaky(s1.w + d1.w)));
    atomicAdd((float4*)(g_den + dst * 8), v0);
    atomicAdd((float4*)(g_den + dst * 8 + 4), v1);
}

// ---------------- K4: weighted scatter (warp per edge) ------------
__global__ void __launch_bounds__(256) k4_scatter(const int* __restrict__ ei,
                                                  float* __restrict__ out) {
    int gt = blockIdx.x * 256 + threadIdx.x;
    int w = gt >> 5, l = gt & 31;
    if (w >= TOT_EDGES) return;
    int src, dst;
    if (w < E_EDGES) { src = __ldg(ei + w); dst = __ldg(ei + E_EDGES + w); }
    else             { src = dst = w - E_EDGES; }
    int h = l >> 2;
    float e = __ldg(g_as + src * 8 + h) + __ldg(g_ad + dst * 8 + h);
    float den = g_den[dst * 8 + h];
    float alpha = expf(leaky(e)) / (den + 1e-16f);
    float4 xv = *(const float4*)(g_x + (size_t)src * D_MODEL + l * 4);
    float4 mv = make_float4(xv.x * alpha, xv.y * alpha, xv.z * alpha, xv.w * alpha);
    atomicAdd((float4*)(out + (size_t)dst * D_MODEL + l * 4), mv);
}

// ---------------- K5: fused LN2 + FFN + residual (bf16-split MMA) ---
// 64 rows per block, 256 threads = 8 warps. Dynamic smem:
//   H2H/H2L:  [64][68]  packed bf16x2 (k-pairs) of LN2 output hi/lo
//   ACTH/ACTL:[64][260] packed bf16x2 of relu(GEMM1) hi/lo
#define SM_H2H  0
#define SM_H2L  4352
#define SM_ACTH 8704
#define SM_ACTL 25344
#define SM_WORDS 41984   // * 4B = 167,936 bytes

__global__ void __launch_bounds__(256) k5_ffn(float* __restrict__ out,
                                              const float* __restrict__ g2,
                                              const float* __restrict__ b2v,
                                              const float* __restrict__ bb1,
                                              const float* __restrict__ bb2) {
    extern __shared__ unsigned sm[];
    unsigned* H2H = sm + SM_H2H;
    unsigned* H2L = sm + SM_H2L;
    unsigned* ACTH = sm + SM_ACTH;
    unsigned* ACTL = sm + SM_ACTL;

    const int t = threadIdx.x;
    const int lane = t & 31, w = t >> 5;
    const int g4 = lane >> 2, q4 = lane & 3;
    const int row0 = blockIdx.x * 64;
    const int valid = min(64, N_NODES - row0);

    // ---- Phase A: LN2, split to bf16 hi/lo, pack k-pairs ----
    {
        int r = t >> 2, q = t & 3;                 // 4 threads/row, 32 elems each
        if (r < valid) {
            int grow = row0 + r;
            const float4* rp = (const float4*)(out + (size_t)grow * D_MODEL + q * 32);
            float v[32];
#pragma unroll
            for (int j = 0; j < 8; j++) {
                float4 x = rp[j];
                v[4 * j] = x.x; v[4 * j + 1] = x.y; v[4 * j + 2] = x.z; v[4 * j + 3] = x.w;
            }
            float s = 0.f, s2 = 0.f;
#pragma unroll
            for (int j = 0; j < 32; j++) { s += v[j]; s2 += v[j] * v[j]; }
            s  += __shfl_xor_sync(0xffffffffu, s, 1);
            s  += __shfl_xor_sync(0xffffffffu, s, 2);
            s2 += __shfl_xor_sync(0xffffffffu, s2, 1);
            s2 += __shfl_xor_sync(0xffffffffu, s2, 2);
            float mean = s * (1.f / 128.f);
            float var = (s2 * (1.f / 128.f) - mean * mean) * (128.f / 127.f);
            float rstd = 1.f / (sqrtf(fmaxf(var, 0.f)) + LN_EPS);
#pragma unroll
            for (int j = 0; j < 16; j++) {
                int c = q * 32 + 2 * j;
                float y0 = g2[c]     * (v[2 * j]     - mean) * rstd + b2v[c];
                float y1 = g2[c + 1] * (v[2 * j + 1] - mean) * rstd + b2v[c + 1];
                unsigned hi, lo;
                split_pack(y0, y1, hi, lo);
                H2H[r * 68 + q * 16 + j] = hi;
                H2L[r * 68 + q * 16 + j] = lo;
            }
        } else {
#pragma unroll
            for (int j = 0; j < 16; j++) {
                H2H[r * 68 + q * 16 + j] = 0u;
                H2L[r * 68 + q * 16 + j] = 0u;
            }
        }
    }
    __syncthreads();

    // ---- Phase B: GEMM1 64x512x128 + bias + relu -> ACT (2 n-chunks) ----
    for (int ch = 0; ch < 2; ch++) {
        const int n0 = w * 64 + ch * 32;
        float acc[4][4][4];                        // [mtile][ntile][frag]
#pragma unroll
        for (int a = 0; a < 4; a++)
#pragma unroll
            for (int b = 0; b < 4; b++)
#pragma unroll
                for (int c = 0; c < 4; c++) acc[a][b][c] = 0.f;

        for (int ks = 0; ks < 8; ks++) {
            unsigned ah[4][4], al[4][4];
#pragma unroll
            for (int mt = 0; mt < 4; mt++) {
                int rr = mt * 16 + g4;
                int cp = ks * 8 + q4;
                ah[mt][0] = H2H[rr * 68 + cp];       ah[mt][1] = H2H[(rr + 8) * 68 + cp];
                ah[mt][2] = H2H[rr * 68 + cp + 4];   ah[mt][3] = H2H[(rr + 8) * 68 + cp + 4];
                al[mt][0] = H2L[rr * 68 + cp];       al[mt][1] = H2L[(rr + 8) * 68 + cp];
                al[mt][2] = H2L[rr * 68 + cp + 4];   al[mt][3] = H2L[(rr + 8) * 68 + cp + 4];
            }
#pragma unroll
            for (int nt = 0; nt < 4; nt++) {
                int n = n0 + nt * 8 + g4;
                int kh = ks * 8 + q4;
                unsigned bh0 = g_w1h[kh * DFF + n], bh1 = g_w1h[(kh + 4) * DFF + n];
                unsigned bl0 = g_w1l[kh * DFF + n], bl1 = g_w1l[(kh + 4) * DFF + n];
#pragma unroll
                for (int mt = 0; mt < 4; mt++) mma16816(acc[mt][nt], ah[mt], bh0, bh1);
#pragma unroll
                for (int mt = 0; mt < 4; mt++) mma16816(acc[mt][nt], ah[mt], bl0, bl1);
#pragma unroll
                for (int mt = 0; mt < 4; mt++) mma16816(acc[mt][nt], al[mt], bh0, bh1);
            }
        }
        // epilogue: bias + relu, split-pack into ACT
#pragma unroll
        for (int nt = 0; nt < 4; nt++) {
            int c = n0 + nt * 8 + q4 * 2;
            float bi0 = bb1[c], bi1 = bb1[c + 1];
            int cp = c >> 1;
#pragma unroll
            for (int mt = 0; mt < 4; mt++) {
                int r1 = mt * 16 + g4, r2 = r1 + 8;
                unsigned hi, lo;
                split_pack(fmaxf(acc[mt][nt][0] + bi0, 0.f),
                           fmaxf(acc[mt][nt][1] + bi1, 0.f), hi, lo);
                ACTH[r1 * 260 + cp] = hi; ACTL[r1 * 260 + cp] = lo;
                split_pack(fmaxf(acc[mt][nt][2] + bi0, 0.f),
                           fmaxf(acc[mt][nt][3] + bi1, 0.f), hi, lo);
                ACTH[r2 * 260 + cp] = hi; ACTL[r2 * 260 + cp] = lo;
            }
        }
    }
    __syncthreads();

    // ---- Phase C: GEMM2 64x128x512 + bias + residual ----
    {
        const int n0 = w * 16;
        float acc[4][2][4];
#pragma unroll
        for (int a = 0; a < 4; a++)
#pragma unroll
            for (int b = 0; b < 2; b++)
#pragma unroll
                for (int c = 0; c < 4; c++) acc[a][b][c] = 0.f;

        for (int ks = 0; ks < 32; ks++) {
            unsigned ah[4][4], al[4][4];
#pragma unroll
            for (int mt = 0; mt < 4; mt++) {
                int rr = mt * 16 + g4;
                int cp = ks * 8 + q4;
                ah[mt][0] = ACTH[rr * 260 + cp];     ah[mt][1] = ACTH[(rr + 8) * 260 + cp];
                ah[mt][2] = ACTH[rr * 260 + cp + 4]; ah[mt][3] = ACTH[(rr + 8) * 260 + cp + 4];
                al[mt][0] = ACTL[rr * 260 + cp];     al[mt][1] = ACTL[(rr + 8) * 260 + cp];
                al[mt][2] = ACTL[rr * 260 + cp + 4]; al[mt][3] = ACTL[(rr + 8) * 260 + cp + 4];
            }
#pragma unroll
            for (int nt = 0; nt < 2; nt++) {
                int n = n0 + nt * 8 + g4;
                int kh = ks * 8 + q4;
                unsigned bh0 = g_w2h[kh * D_MODEL + n], bh1 = g_w2h[(kh + 4) * D_MODEL + n];
                unsigned bl0 = g_w2l[kh * D_MODEL + n], bl1 = g_w2l[(kh + 4) * D_MODEL + n];
#pragma unroll
                for (int mt = 0; mt < 4; mt++) mma16816(acc[mt][nt], ah[mt], bh0, bh1);
#pragma unroll
                for (int mt = 0; mt < 4; mt++) mma16816(acc[mt][nt], ah[mt], bl0, bl1);
#pragma unroll
                for (int mt = 0; mt < 4; mt++) mma16816(acc[mt][nt], al[mt], bh0, bh1);
            }
        }
        // epilogue: + bias + residual
#pragma unroll
        for (int nt = 0; nt < 2; nt++) {
            int c = n0 + nt * 8 + q4 * 2;
            float bi0 = bb2[c], bi1 = bb2[c + 1];
#pragma unroll
            for (int mt = 0; mt < 4; mt++) {
                int lr1 = mt * 16 + g4, lr2 = lr1 + 8;
                if (lr1 < valid) {
                    float* p = out + (size_t)(row0 + lr1) * D_MODEL + c;
                    float2 o = *(float2*)p;
                    o.x += acc[mt][nt][0] + bi0;
                    o.y += acc[mt][nt][1] + bi1;
                    *(float2*)p = o;
                }
                if (lr2 < valid) {
                    float* p = out + (size_t)(row0 + lr2) * D_MODEL + c;
                    float2 o = *(float2*)p;
                    o.x += acc[mt][nt][2] + bi0;
                    o.y += acc[mt][nt][3] + bi1;
                    *(float2*)p = o;
                }
            }
        }
    }
}

// ---------------- host launcher -----------------------------------
extern "C" void kernel_launch(void* const* d_in, const int* in_sizes, int n_in,
                              void* d_out, int out_size) {
    const float* nf       = (const float*)d_in[0];
    const int*   ei       = (const int*)d_in[1];     // JAX demotes int64 -> int32
    const float* ln1_g    = (const float*)d_in[2];
    const float* ln1_b    = (const float*)d_in[3];
    const float* W_att    = (const float*)d_in[4];
    const float* att_src  = (const float*)d_in[5];
    const float* att_dst  = (const float*)d_in[6];
    const float* bias_att = (const float*)d_in[7];
    const float* ln2_g    = (const float*)d_in[8];
    const float* ln2_b    = (const float*)d_in[9];
    const float* W1       = (const float*)d_in[10];
    const float* b1       = (const float*)d_in[11];
    const float* W2       = (const float*)d_in[12];
    const float* b2       = (const float*)d_in[13];
    float* out = (float*)d_out;

    static int smem_set = 0;
    if (!smem_set) {
        cudaFuncSetAttribute(k5_ffn, cudaFuncAttributeMaxDynamicSharedMemorySize,
                             SM_WORDS * 4);
        smem_set = 1;
    }

    // weight split (independent of everything else)
    kprep<<<(64 * DFF + 256 * D_MODEL) / 256, 256>>>(W1, W2);
    // K0: residual init + denominator clear
    k0_init<<<(N_NODES * D_MODEL / 4 + 255) / 256, 256>>>(nf, bias_att, out);
    // K1: LN1 + projection + attention logits
    k1_ln_proj<<<N_NODES / 16, 128>>>(nf, ln1_g, ln1_b, W_att, att_src, att_dst);
    // K3: softmax denominators (no max shift needed)
    k3_den<<<(TOT_EDGES + 255) / 256, 256>>>(ei);
    // K4: weighted message scatter (one warp per edge)
    k4_scatter<<<((size_t)TOT_EDGES * 32 + 255) / 256, 256>>>(ei, out);
    // K5: fused LN2 + FFN + residual on tensor cores
    k5_ffn<<<(N_NODES + 63) / 64, 256, SM_WORDS * 4>>>(out, ln2_g, ln2_b, b1, b2);
}

// round 4
// speedup vs baseline: 2.1247x; 1.0899x over previous
#include <cuda_runtime.h>
#include <cuda_bf16.h>
#include <math.h>

#define N_NODES 50000
#define D_MODEL 128
#define H_HEADS 8
#define DH 16
#define DFF 512
#define E_EDGES 800000
#define TOT_EDGES (E_EDGES + N_NODES)   // self loops appended
#define LN_EPS 1e-6f
#define NEG_SLOPE 0.2f

// ---------------- scratch (no allocations allowed) ----------------
__device__ __align__(16) float g_x[(size_t)N_NODES * D_MODEL];   // projected features [N,128]
__device__ __align__(16) float g_as[N_NODES * H_HEADS];          // alpha_src logits
__device__ __align__(16) float g_ad[N_NODES * H_HEADS];          // alpha_dst logits
__device__ __align__(16) float g_den[N_NODES * H_HEADS];         // softmax denom -> reciprocal
// bf16 split-precision weights, packed 2 consecutive k per word
__device__ __align__(16) unsigned g_w1h[64 * DFF];               // W1 hi  [kpair][n]
__device__ __align__(16) unsigned g_w1l[64 * DFF];               // W1 lo
__device__ __align__(16) unsigned g_w2h[256 * D_MODEL];          // W2 hi  [kpair][n]
__device__ __align__(16) unsigned g_w2l[256 * D_MODEL];          // W2 lo
__device__ __align__(16) unsigned g_wAh[64 * D_MODEL];           // W_att hi [kpair][n]
__device__ __align__(16) unsigned g_wAl[64 * D_MODEL];           // W_att lo

__device__ __forceinline__ float leaky(float x) { return x > 0.f ? x : NEG_SLOPE * x; }

// split x0,x1 into packed bf16x2 hi and lo words (low half = x0)
__device__ __forceinline__ void split_pack(float x0, float x1, unsigned& hi, unsigned& lo) {
    __nv_bfloat162 h = __floats2bfloat162_rn(x0, x1);
    float2 hf = __bfloat1622float2(h);
    __nv_bfloat162 l = __floats2bfloat162_rn(x0 - hf.x, x1 - hf.y);
    hi = *reinterpret_cast<unsigned*>(&h);
    lo = *reinterpret_cast<unsigned*>(&l);
}

// D += A(16x16) * B(16x8), bf16 inputs, fp32 accum
__device__ __forceinline__ void mma16816(float* c, const unsigned* a, unsigned b0, unsigned b1) {
    asm volatile(
        "mma.sync.aligned.m16n8k16.row.col.f32.bf16.bf16.f32 "
        "{%0,%1,%2,%3}, {%4,%5,%6,%7}, {%8,%9}, {%0,%1,%2,%3};"
        : "+f"(c[0]), "+f"(c[1]), "+f"(c[2]), "+f"(c[3])
        : "r"(a[0]), "r"(a[1]), "r"(a[2]), "r"(a[3]), "r"(b0), "r"(b1));
}

// ---------------- Kprep: split W1/W2/W_att into bf16 hi/lo ---------
__global__ void __launch_bounds__(256) kprep(const float* __restrict__ W1,
                                             const float* __restrict__ W2,
                                             const float* __restrict__ WA) {
    int i = blockIdx.x * 256 + threadIdx.x;
    if (i < 64 * DFF) {
        int kh = i / DFF, n = i % DFF;
        split_pack(W1[(2 * kh) * DFF + n], W1[(2 * kh + 1) * DFF + n], g_w1h[i], g_w1l[i]);
    } else if (i < 64 * DFF + 256 * D_MODEL) {
        int j = i - 64 * DFF;
        int kh = j / D_MODEL, n = j % D_MODEL;
        split_pack(W2[(2 * kh) * D_MODEL + n], W2[(2 * kh + 1) * D_MODEL + n], g_w2h[j], g_w2l[j]);
    } else {
        int j = i - 64 * DFF - 256 * D_MODEL;  // < 64*128
        int kh = j / D_MODEL, n = j % D_MODEL;
        split_pack(WA[(2 * kh) * D_MODEL + n], WA[(2 * kh + 1) * D_MODEL + n], g_wAh[j], g_wAl[j]);
    }
}

// ---------------- K1: LN1 -> x = h1 @ W_att (MMA); a_s, a_d; out=nf+bias
// 64 rows per block, 256 threads = 8 warps.
// Dynamic smem: H1H/H1L [64][68] packed bf16x2 (8704 words), aliased by
// XS [64][132] fp32 GEMM result (8448 words) after phase B.
__global__ void __launch_bounds__(256) k1_ln_proj(const float* __restrict__ nf,
                                                  const float* __restrict__ g1,
                                                  const float* __restrict__ b1v,
                                                  const float* __restrict__ bias_att,
                                                  const float* __restrict__ asrc,
                                                  const float* __restrict__ adst,
                                                  float* __restrict__ out) {
    extern __shared__ unsigned sm[];
    unsigned* H1H = sm;
    unsigned* H1L = sm + 4352;
    float* XS = (float*)sm;              // aliases H1 after phase B

    const int t = threadIdx.x;
    const int lane = t & 31, w = t >> 5;
    const int g4 = lane >> 2, q4 = lane & 3;
    const int row0 = blockIdx.x * 64;
    const int valid = min(64, N_NODES - row0);

    // clear g_den for this row range
    {
        int base = row0 * 8;
#pragma unroll
        for (int j = 0; j < 2; j++) {
            int idx = base + t + j * 256;
            if (idx < N_NODES * 8) g_den[idx] = 0.f;
        }
    }

    // ---- Phase A: LN1, out = nf + bias_att, split to bf16 hi/lo ----
    {
        int r = t >> 2, q = t & 3;
        if (r < valid) {
            int grow = row0 + r;
            const float4* rp = (const float4*)(nf + (size_t)grow * D_MODEL + q * 32);
            float v[32];
#pragma unroll
            for (int j = 0; j < 8; j++) {
                float4 x = rp[j];
                v[4 * j] = x.x; v[4 * j + 1] = x.y; v[4 * j + 2] = x.z; v[4 * j + 3] = x.w;
            }
            // residual init: out = nf + bias_att
            float4* op = (float4*)(out + (size_t)grow * D_MODEL + q * 32);
#pragma unroll
            for (int j = 0; j < 8; j++) {
                int c = q * 32 + 4 * j;
                op[j] = make_float4(v[4 * j]     + __ldg(bias_att + c),
                                    v[4 * j + 1] + __ldg(bias_att + c + 1),
                                    v[4 * j + 2] + __ldg(bias_att + c + 2),
                                    v[4 * j + 3] + __ldg(bias_att + c + 3));
            }
            float s = 0.f, s2 = 0.f;
#pragma unroll
            for (int j = 0; j < 32; j++) { s += v[j]; s2 += v[j] * v[j]; }
            s  += __shfl_xor_sync(0xffffffffu, s, 1);
            s  += __shfl_xor_sync(0xffffffffu, s, 2);
            s2 += __shfl_xor_sync(0xffffffffu, s2, 1);
            s2 += __shfl_xor_sync(0xffffffffu, s2, 2);
            float mean = s * (1.f / 128.f);
            float var = (s2 * (1.f / 128.f) - mean * mean) * (128.f / 127.f);
            float rstd = 1.f / (sqrtf(fmaxf(var, 0.f)) + LN_EPS);
#pragma unroll
            for (int j = 0; j < 16; j++) {
                int c = q * 32 + 2 * j;
                float y0 = __ldg(g1 + c)     * (v[2 * j]     - mean) * rstd + __ldg(b1v + c);
                float y1 = __ldg(g1 + c + 1) * (v[2 * j + 1] - mean) * rstd + __ldg(b1v + c + 1);
                unsigned hi, lo;
                split_pack(y0, y1, hi, lo);
                H1H[r * 68 + q * 16 + j] = hi;
                H1L[r * 68 + q * 16 + j] = lo;
            }
        } else {
            int r2 = t >> 2, q2 = t & 3;
#pragma unroll
            for (int j = 0; j < 16; j++) {
                H1H[r2 * 68 + q2 * 16 + j] = 0u;
                H1L[r2 * 68 + q2 * 16 + j] = 0u;
            }
        }
    }
    __syncthreads();

    // ---- Phase B: GEMM 64x128x128 ----
    const int n0 = w * 16;
    float acc[4][2][4];
#pragma unroll
    for (int a = 0; a < 4; a++)
#pragma unroll
        for (int b = 0; b < 2; b++)
#pragma unroll
            for (int c = 0; c < 4; c++) acc[a][b][c] = 0.f;

    for (int ks = 0; ks < 8; ks++) {
        unsigned ah[4][4], al[4][4];
#pragma unroll
        for (int mt = 0; mt < 4; mt++) {
            int rr = mt * 16 + g4;
            int cp = ks * 8 + q4;
            ah[mt][0] = H1H[rr * 68 + cp];       ah[mt][1] = H1H[(rr + 8) * 68 + cp];
            ah[mt][2] = H1H[rr * 68 + cp + 4];   ah[mt][3] = H1H[(rr + 8) * 68 + cp + 4];
            al[mt][0] = H1L[rr * 68 + cp];       al[mt][1] = H1L[(rr + 8) * 68 + cp];
            al[mt][2] = H1L[rr * 68 + cp + 4];   al[mt][3] = H1L[(rr + 8) * 68 + cp + 4];
        }
#pragma unroll
        for (int nt = 0; nt < 2; nt++) {
            int n = n0 + nt * 8 + g4;
            int kh = ks * 8 + q4;
            unsigned bh0 = __ldg(&g_wAh[kh * D_MODEL + n]), bh1 = __ldg(&g_wAh[(kh + 4) * D_MODEL + n]);
            unsigned bl0 = __ldg(&g_wAl[kh * D_MODEL + n]), bl1 = __ldg(&g_wAl[(kh + 4) * D_MODEL + n]);
#pragma unroll
            for (int mt = 0; mt < 4; mt++) mma16816(acc[mt][nt], ah[mt], bh0, bh1);
#pragma unroll
            for (int mt = 0; mt < 4; mt++) mma16816(acc[mt][nt], ah[mt], bl0, bl1);
#pragma unroll
            for (int mt = 0; mt < 4; mt++) mma16816(acc[mt][nt], al[mt], bh0, bh1);
        }
    }
    __syncthreads();   // all H1 reads done; XS may overwrite

    // ---- stage result in XS [64][132] ----
#pragma unroll
    for (int nt = 0; nt < 2; nt++) {
        int c = n0 + nt * 8 + q4 * 2;
#pragma unroll
        for (int mt = 0; mt < 4; mt++) {
            int r1 = mt * 16 + g4, r2 = r1 + 8;
            XS[r1 * 132 + c]     = acc[mt][nt][0];
            XS[r1 * 132 + c + 1] = acc[mt][nt][1];
            XS[r2 * 132 + c]     = acc[mt][nt][2];
            XS[r2 * 132 + c + 1] = acc[mt][nt][3];
        }
    }
    __syncthreads();

    // ---- write g_x (coalesced) ----
    for (int idx = t; idx < 64 * 32; idx += 256) {
        int row = idx >> 5, c4 = idx & 31;
        if (row < valid)
            *(float4*)(g_x + (size_t)(row0 + row) * D_MODEL + c4 * 4) =
                *(float4*)&XS[row * 132 + c4 * 4];
    }

    // ---- attention logits: warp w handles rows w*8..w*8+7 ----
    {
        int row = w * 8 + (lane >> 2);
        int h0 = q4 * 2;                 // each lane owns heads h0, h0+1
        if (row < valid) {
            float ps0 = 0.f, pd0 = 0.f, ps1 = 0.f, pd1 = 0.f;
#pragma unroll
            for (int j = 0; j < 16; j++) {
                float x0 = XS[row * 132 + h0 * 16 + j];
                float x1 = XS[row * 132 + (h0 + 1) * 16 + j];
                ps0 += x0 * __ldg(asrc + h0 * DH + j);
                pd0 += x0 * __ldg(adst + h0 * DH + j);
                ps1 += x1 * __ldg(asrc + (h0 + 1) * DH + j);
                pd1 += x1 * __ldg(adst + (h0 + 1) * DH + j);
            }
            int grow = row0 + row;
            g_as[grow * 8 + h0] = ps0;     g_ad[grow * 8 + h0] = pd0;
            g_as[grow * 8 + h0 + 1] = ps1; g_ad[grow * 8 + h0 + 1] = pd1;
        }
    }
}

// ---------------- K3: softmax denominators (no max shift) ----------
__global__ void __launch_bounds__(256) k3_den(const int* __restrict__ ei) {
    int e = blockIdx.x * 256 + threadIdx.x;
    if (e >= TOT_EDGES) return;
    int src, dst;
    if (e < E_EDGES) { src = __ldg(ei + e); dst = __ldg(ei + E_EDGES + e); }
    else             { src = dst = e - E_EDGES; }
    float4 s0 = *(const float4*)(g_as + src * 8);
    float4 s1 = *(const float4*)(g_as + src * 8 + 4);
    float4 d0 = *(const float4*)(g_ad + dst * 8);
    float4 d1 = *(const float4*)(g_ad + dst * 8 + 4);
    float4 v0 = make_float4(expf(leaky(s0.x + d0.x)), expf(leaky(s0.y + d0.y)),
                            expf(leaky(s0.z + d0.z)), expf(leaky(s0.w + d0.w)));
    float4 v1 = make_float4(expf(leaky(s1.x + d1.x)), expf(leaky(s1.y + d1.y)),
                            expf(leaky(s1.z + d1.z)), expf(leaky(s1.w + d1.w)));
    atomicAdd((float4*)(g_den + dst * 8), v0);
    atomicAdd((float4*)(g_den + dst * 8 + 4), v1);
}

// ---------------- K3b: invert denominators in place ----------------
__global__ void __launch_bounds__(256) k3b_rcp() {
    int i = blockIdx.x * 256 + threadIdx.x;
    if (i < N_NODES * H_HEADS) g_den[i] = 1.f / (g_den[i] + 1e-16f);
}

// ---------------- K4: weighted scatter (warp per edge) ------------
__global__ void __launch_bounds__(256) k4_scatter(const int* __restrict__ ei,
                                                  float* __restrict__ out) {
    int gt = blockIdx.x * 256 + threadIdx.x;
    int w = gt >> 5, l = gt & 31;
    if (w >= TOT_EDGES) return;
    int src, dst;
    if (w < E_EDGES) { src = __ldg(ei + w); dst = __ldg(ei + E_EDGES + w); }
    else             { src = dst = w - E_EDGES; }
    int h = l >> 2;
    float e = __ldg(g_as + src * 8 + h) + __ldg(g_ad + dst * 8 + h);
    float alpha = expf(leaky(e)) * __ldg(g_den + dst * 8 + h);
    float4 xv = *(const float4*)(g_x + (size_t)src * D_MODEL + l * 4);
    float4 mv = make_float4(xv.x * alpha, xv.y * alpha, xv.z * alpha, xv.w * alpha);
    atomicAdd((float4*)(out + (size_t)dst * D_MODEL + l * 4), mv);
}

// ---------------- K5: fused LN2 + FFN + residual (bf16-split MMA) ---
#define SM_H2H  0
#define SM_H2L  4352
#define SM_ACTH 8704
#define SM_ACTL 25344
#define SM_WORDS 41984   // * 4B = 167,936 bytes

__global__ void __launch_bounds__(256) k5_ffn(float* __restrict__ out,
                                              const float* __restrict__ g2,
                                              const float* __restrict__ b2v,
                                              const float* __restrict__ bb1,
                                              const float* __restrict__ bb2) {
    extern __shared__ unsigned sm[];
    unsigned* H2H = sm + SM_H2H;
    unsigned* H2L = sm + SM_H2L;
    unsigned* ACTH = sm + SM_ACTH;
    unsigned* ACTL = sm + SM_ACTL;

    const int t = threadIdx.x;
    const int lane = t & 31, w = t >> 5;
    const int g4 = lane >> 2, q4 = lane & 3;
    const int row0 = blockIdx.x * 64;
    const int valid = min(64, N_NODES - row0);

    // ---- Phase A: LN2, split to bf16 hi/lo, pack k-pairs ----
    {
        int r = t >> 2, q = t & 3;
        if (r < valid) {
            int grow = row0 + r;
            const float4* rp = (const float4*)(out + (size_t)grow * D_MODEL + q * 32);
            float v[32];
#pragma unroll
            for (int j = 0; j < 8; j++) {
                float4 x = rp[j];
                v[4 * j] = x.x; v[4 * j + 1] = x.y; v[4 * j + 2] = x.z; v[4 * j + 3] = x.w;
            }
            float s = 0.f, s2 = 0.f;
#pragma unroll
            for (int j = 0; j < 32; j++) { s += v[j]; s2 += v[j] * v[j]; }
            s  += __shfl_xor_sync(0xffffffffu, s, 1);
            s  += __shfl_xor_sync(0xffffffffu, s, 2);
            s2 += __shfl_xor_sync(0xffffffffu, s2, 1);
            s2 += __shfl_xor_sync(0xffffffffu, s2, 2);
            float mean = s * (1.f / 128.f);
            float var = (s2 * (1.f / 128.f) - mean * mean) * (128.f / 127.f);
            float rstd = 1.f / (sqrtf(fmaxf(var, 0.f)) + LN_EPS);
#pragma unroll
            for (int j = 0; j < 16; j++) {
                int c = q * 32 + 2 * j;
                float y0 = __ldg(g2 + c)     * (v[2 * j]     - mean) * rstd + __ldg(b2v + c);
                float y1 = __ldg(g2 + c + 1) * (v[2 * j + 1] - mean) * rstd + __ldg(b2v + c + 1);
                unsigned hi, lo;
                split_pack(y0, y1, hi, lo);
                H2H[r * 68 + q * 16 + j] = hi;
                H2L[r * 68 + q * 16 + j] = lo;
            }
        } else {
#pragma unroll
            for (int j = 0; j < 16; j++) {
                H2H[r * 68 + q * 16 + j] = 0u;
                H2L[r * 68 + q * 16 + j] = 0u;
            }
        }
    }
    __syncthreads();

    // ---- Phase B: GEMM1 64x512x128 + bias + relu -> ACT (2 n-chunks) ----
    for (int ch = 0; ch < 2; ch++) {
        const int n0 = w * 64 + ch * 32;
        float acc[4][4][4];
#pragma unroll
        for (int a = 0; a < 4; a++)
#pragma unroll
            for (int b = 0; b < 4; b++)
#pragma unroll
                for (int c = 0; c < 4; c++) acc[a][b][c] = 0.f;

        for (int ks = 0; ks < 8; ks++) {
            unsigned ah[4][4], al[4][4];
#pragma unroll
            for (int mt = 0; mt < 4; mt++) {
                int rr = mt * 16 + g4;
                int cp = ks * 8 + q4;
                ah[mt][0] = H2H[rr * 68 + cp];       ah[mt][1] = H2H[(rr + 8) * 68 + cp];
                ah[mt][2] = H2H[rr * 68 + cp + 4];   ah[mt][3] = H2H[(rr + 8) * 68 + cp + 4];
                al[mt][0] = H2L[rr * 68 + cp];       al[mt][1] = H2L[(rr + 8) * 68 + cp];
                al[mt][2] = H2L[rr * 68 + cp + 4];   al[mt][3] = H2L[(rr + 8) * 68 + cp + 4];
            }
#pragma unroll
            for (int nt = 0; nt < 4; nt++) {
                int n = n0 + nt * 8 + g4;
                int kh = ks * 8 + q4;
                unsigned bh0 = __ldg(&g_w1h[kh * DFF + n]), bh1 = __ldg(&g_w1h[(kh + 4) * DFF + n]);
                unsigned bl0 = __ldg(&g_w1l[kh * DFF + n]), bl1 = __ldg(&g_w1l[(kh + 4) * DFF + n]);
#pragma unroll
                for (int mt = 0; mt < 4; mt++) mma16816(acc[mt][nt], ah[mt], bh0, bh1);
#pragma unroll
                for (int mt = 0; mt < 4; mt++) mma16816(acc[mt][nt], ah[mt], bl0, bl1);
#pragma unroll
                for (int mt = 0; mt < 4; mt++) mma16816(acc[mt][nt], al[mt], bh0, bh1);
            }
        }
#pragma unroll
        for (int nt = 0; nt < 4; nt++) {
            int c = n0 + nt * 8 + q4 * 2;
            float bi0 = __ldg(bb1 + c), bi1 = __ldg(bb1 + c + 1);
            int cp = c >> 1;
#pragma unroll
            for (int mt = 0; mt < 4; mt++) {
                int r1 = mt * 16 + g4, r2 = r1 + 8;
                unsigned hi, lo;
                split_pack(fmaxf(acc[mt][nt][0] + bi0, 0.f),
                           fmaxf(acc[mt][nt][1] + bi1, 0.f), hi, lo);
                ACTH[r1 * 260 + cp] = hi; ACTL[r1 * 260 + cp] = lo;
                split_pack(fmaxf(acc[mt][nt][2] + bi0, 0.f),
                           fmaxf(acc[mt][nt][3] + bi1, 0.f), hi, lo);
                ACTH[r2 * 260 + cp] = hi; ACTL[r2 * 260 + cp] = lo;
            }
        }
    }
    __syncthreads();

    // ---- Phase C: GEMM2 64x128x512 + bias + residual ----
    {
        const int n0 = w * 16;
        float acc[4][2][4];
#pragma unroll
        for (int a = 0; a < 4; a++)
#pragma unroll
            for (int b = 0; b < 2; b++)
#pragma unroll
                for (int c = 0; c < 4; c++) acc[a][b][c] = 0.f;

        for (int ks = 0; ks < 32; ks++) {
            unsigned ah[4][4], al[4][4];
#pragma unroll
            for (int mt = 0; mt < 4; mt++) {
                int rr = mt * 16 + g4;
                int cp = ks * 8 + q4;
                ah[mt][0] = ACTH[rr * 260 + cp];     ah[mt][1] = ACTH[(rr + 8) * 260 + cp];
                ah[mt][2] = ACTH[rr * 260 + cp + 4]; ah[mt][3] = ACTH[(rr + 8) * 260 + cp + 4];
                al[mt][0] = ACTL[rr * 260 + cp];     al[mt][1] = ACTL[(rr + 8) * 260 + cp];
                al[mt][2] = ACTL[rr * 260 + cp + 4]; al[mt][3] = ACTL[(rr + 8) * 260 + cp + 4];
            }
#pragma unroll
            for (int nt = 0; nt < 2; nt++) {
                int n = n0 + nt * 8 + g4;
                int kh = ks * 8 + q4;
                unsigned bh0 = __ldg(&g_w2h[kh * D_MODEL + n]), bh1 = __ldg(&g_w2h[(kh + 4) * D_MODEL + n]);
                unsigned bl0 = __ldg(&g_w2l[kh * D_MODEL + n]), bl1 = __ldg(&g_w2l[(kh + 4) * D_MODEL + n]);
#pragma unroll
                for (int mt = 0; mt < 4; mt++) mma16816(acc[mt][nt], ah[mt], bh0, bh1);
#pragma unroll
                for (int mt = 0; mt < 4; mt++) mma16816(acc[mt][nt], ah[mt], bl0, bl1);
#pragma unroll
                for (int mt = 0; mt < 4; mt++) mma16816(acc[mt][nt], al[mt], bh0, bh1);
            }
        }
#pragma unroll
        for (int nt = 0; nt < 2; nt++) {
            int c = n0 + nt * 8 + q4 * 2;
            float bi0 = __ldg(bb2 + c), bi1 = __ldg(bb2 + c + 1);
#pragma unroll
            for (int mt = 0; mt < 4; mt++) {
                int lr1 = mt * 16 + g4, lr2 = lr1 + 8;
                if (lr1 < valid) {
                    float* p = out + (size_t)(row0 + lr1) * D_MODEL + c;
                    float2 o = *(float2*)p;
                    o.x += acc[mt][nt][0] + bi0;
                    o.y += acc[mt][nt][1] + bi1;
                    *(float2*)p = o;
                }
                if (lr2 < valid) {
                    float* p = out + (size_t)(row0 + lr2) * D_MODEL + c;
                    float2 o = *(float2*)p;
                    o.x += acc[mt][nt][2] + bi0;
                    o.y += acc[mt][nt][3] + bi1;
                    *(float2*)p = o;
                }
            }
        }
    }
}

// ---------------- host launcher -----------------------------------
extern "C" void kernel_launch(void* const* d_in, const int* in_sizes, int n_in,
                              void* d_out, int out_size) {
    const float* nf       = (const float*)d_in[0];
    const int*   ei       = (const int*)d_in[1];     // JAX demotes int64 -> int32
    const float* ln1_g    = (const float*)d_in[2];
    const float* ln1_b    = (const float*)d_in[3];
    const float* W_att    = (const float*)d_in[4];
    const float* att_src  = (const float*)d_in[5];
    const float* att_dst  = (const float*)d_in[6];
    const float* bias_att = (const float*)d_in[7];
    const float* ln2_g    = (const float*)d_in[8];
    const float* ln2_b    = (const float*)d_in[9];
    const float* W1       = (const float*)d_in[10];
    const float* b1       = (const float*)d_in[11];
    const float* W2       = (const float*)d_in[12];
    const float* b2       = (const float*)d_in[13];
    float* out = (float*)d_out;

    static int smem_set = 0;
    if (!smem_set) {
        cudaFuncSetAttribute(k5_ffn, cudaFuncAttributeMaxDynamicSharedMemorySize,
                             SM_WORDS * 4);
        smem_set = 1;
    }

    // weight split: W1 + W2 + W_att
    kprep<<<(64 * DFF + 256 * D_MODEL + 64 * D_MODEL) / 256, 256>>>(W1, W2, W_att);
    // K1: out=nf+bias, LN1 + projection (MMA) + attention logits + den clear
    k1_ln_proj<<<(N_NODES + 63) / 64, 256, 8704 * 4>>>(nf, ln1_g, ln1_b, bias_att,
                                                       att_src, att_dst, out);
    // K3: softmax denominators
    k3_den<<<(TOT_EDGES + 255) / 256, 256>>>(ei);
    // K3b: reciprocal
    k3b_rcp<<<(N_NODES * H_HEADS + 255) / 256, 256>>>();
    // K4: weighted message scatter (one warp per edge)
    k4_scatter<<<((size_t)TOT_EDGES * 32 + 255) / 256, 256>>>(ei, out);
    // K5: fused LN2 + FFN + residual on tensor cores
    k5_ffn<<<(N_NODES + 63) / 64, 256, SM_WORDS * 4>>>(out, ln2_g, ln2_b, b1, b2);
}

// round 5
// speedup vs baseline: 2.2888x; 1.0772x over previous
#include <cuda_runtime.h>
#include <cuda_bf16.h>
#include <math.h>

#define N_NODES 50000
#define D_MODEL 128
#define H_HEADS 8
#define DH 16
#define DFF 512
#define E_EDGES 800000
#define TOT_EDGES (E_EDGES + N_NODES)   // self loops appended
#define LN_EPS 1e-6f
#define NEG_SLOPE 0.2f

// ---------------- scratch (no allocations allowed) ----------------
__device__ __align__(16) float g_x[(size_t)N_NODES * D_MODEL];   // projected features [N,128]
__device__ __align__(16) float g_as[N_NODES * H_HEADS];          // alpha_src logits
__device__ __align__(16) float g_ad[N_NODES * H_HEADS];          // alpha_dst logits
__device__ __align__(16) float g_den[N_NODES * H_HEADS];         // softmax denom -> reciprocal
// packed split-bf16 weights: uint4 = (hi[kh], hi[kh+4], lo[kh], lo[kh+4])
// indexed [khIdx][n] with khIdx = (kh>>3)*4 + (kh&3), kh = k-pair id
__device__ __align__(16) uint4 g_w1p[32 * DFF];                  // W1 (k=128 -> 32 khIdx)
__device__ __align__(16) uint4 g_w2p[128 * D_MODEL];             // W2 (k=512 -> 128 khIdx)
__device__ __align__(16) uint4 g_wAp[32 * D_MODEL];              // W_att

__device__ __forceinline__ float leaky(float x) { return x > 0.f ? x : NEG_SLOPE * x; }

// split x0,x1 into packed bf16x2 hi and lo words (low half = x0)
__device__ __forceinline__ void split_pack(float x0, float x1, unsigned& hi, unsigned& lo) {
    __nv_bfloat162 h = __floats2bfloat162_rn(x0, x1);
    float2 hf = __bfloat1622float2(h);
    __nv_bfloat162 l = __floats2bfloat162_rn(x0 - hf.x, x1 - hf.y);
    hi = *reinterpret_cast<unsigned*>(&h);
    lo = *reinterpret_cast<unsigned*>(&l);
}

// D += A(16x16) * B(16x8), bf16 inputs, fp32 accum
__device__ __forceinline__ void mma16816(float* c, const unsigned* a, unsigned b0, unsigned b1) {
    asm volatile(
        "mma.sync.aligned.m16n8k16.row.col.f32.bf16.bf16.f32 "
        "{%0,%1,%2,%3}, {%4,%5,%6,%7}, {%8,%9}, {%0,%1,%2,%3};"
        : "+f"(c[0]), "+f"(c[1]), "+f"(c[2]), "+f"(c[3])
        : "r"(a[0]), "r"(a[1]), "r"(a[2]), "r"(a[3]), "r"(b0), "r"(b1));
}

// ldmatrix x4: loads a full 16x16 bf16 A-fragment (a0..a3)
__device__ __forceinline__ void ldsm_x4(unsigned* r, unsigned addr) {
    asm volatile("ldmatrix.sync.aligned.m8n8.x4.shared.b16 {%0,%1,%2,%3}, [%4];"
        : "=r"(r[0]), "=r"(r[1]), "=r"(r[2]), "=r"(r[3]) : "r"(addr));
}

__device__ __forceinline__ unsigned smem_u32(const void* p) {
    return (unsigned)__cvta_generic_to_shared(p);
}

// ---------------- Kprep: split + pack weights ----------------------
// entries: W1 32*512=16384, W2 128*128=16384, WA 32*128=4096 -> 36864 (144 blocks)
__global__ void __launch_bounds__(256) kprep(const float* __restrict__ W1,
                                             const float* __restrict__ W2,
                                             const float* __restrict__ WA) {
    int i = blockIdx.x * 256 + threadIdx.x;
    const float* W; int cols, idx; uint4* dst;
    if (i < 32 * DFF)                       { W = W1; cols = DFF;     idx = i;                       dst = g_w1p; }
    else if (i < 32 * DFF + 128 * D_MODEL)  { W = W2; cols = D_MODEL; idx = i - 32 * DFF;            dst = g_w2p; }
    else                                    { W = WA; cols = D_MODEL; idx = i - 32 * DFF - 128 * D_MODEL; dst = g_wAp; }
    int khi = idx / cols, n = idx % cols;
    int ks = khi >> 2, q = khi & 3;
    int kh = ks * 8 + q;
    unsigned h0, l0, h1, l1;
    split_pack(W[(2 * kh) * cols + n],     W[(2 * kh + 1) * cols + n], h0, l0);
    split_pack(W[(2 * kh + 8) * cols + n], W[(2 * kh + 9) * cols + n], h1, l1);
    dst[idx] = make_uint4(h0, h1, l0, l1);
}

// ---------------- K1: LN1 -> x = h1 @ W_att (MMA); a_s, a_d; out=nf+bias
__global__ void __launch_bounds__(256) k1_ln_proj(const float* __restrict__ nf,
                                                  const float* __restrict__ g1,
                                                  const float* __restrict__ b1v,
                                                  const float* __restrict__ bias_att,
                                                  const float* __restrict__ asrc,
                                                  const float* __restrict__ adst,
                                                  float* __restrict__ out) {
    extern __shared__ unsigned sm[];
    unsigned* H1H = sm;
    unsigned* H1L = sm + 4352;
    float* XS = (float*)sm;              // aliases H1 after phase B

    const int t = threadIdx.x;
    const int lane = t & 31, w = t >> 5;
    const int g4 = lane >> 2, q4 = lane & 3;
    const int row0 = blockIdx.x * 64;
    const int valid = min(64, N_NODES - row0);

    // clear g_den for this row range
    {
        int base = row0 * 8;
#pragma unroll
        for (int j = 0; j < 2; j++) {
            int idx = base + t + j * 256;
            if (idx < N_NODES * 8) g_den[idx] = 0.f;
        }
    }

    // ---- Phase A: LN1, out = nf + bias_att, split to bf16 hi/lo ----
    {
        int r = t >> 2, q = t & 3;
        if (r < valid) {
            int grow = row0 + r;
            const float4* rp = (const float4*)(nf + (size_t)grow * D_MODEL + q * 32);
            float v[32];
#pragma unroll
            for (int j = 0; j < 8; j++) {
                float4 x = rp[j];
                v[4 * j] = x.x; v[4 * j + 1] = x.y; v[4 * j + 2] = x.z; v[4 * j + 3] = x.w;
            }
            float4* op = (float4*)(out + (size_t)grow * D_MODEL + q * 32);
#pragma unroll
            for (int j = 0; j < 8; j++) {
                int c = q * 32 + 4 * j;
                op[j] = make_float4(v[4 * j]     + __ldg(bias_att + c),
                                    v[4 * j + 1] + __ldg(bias_att + c + 1),
                                    v[4 * j + 2] + __ldg(bias_att + c + 2),
                                    v[4 * j + 3] + __ldg(bias_att + c + 3));
            }
            float s = 0.f, s2 = 0.f;
#pragma unroll
            for (int j = 0; j < 32; j++) { s += v[j]; s2 += v[j] * v[j]; }
            s  += __shfl_xor_sync(0xffffffffu, s, 1);
            s  += __shfl_xor_sync(0xffffffffu, s, 2);
            s2 += __shfl_xor_sync(0xffffffffu, s2, 1);
            s2 += __shfl_xor_sync(0xffffffffu, s2, 2);
            float mean = s * (1.f / 128.f);
            float var = (s2 * (1.f / 128.f) - mean * mean) * (128.f / 127.f);
            float rstd = 1.f / (sqrtf(fmaxf(var, 0.f)) + LN_EPS);
#pragma unroll
            for (int j = 0; j < 16; j++) {
                int c = q * 32 + 2 * j;
                float y0 = __ldg(g1 + c)     * (v[2 * j]     - mean) * rstd + __ldg(b1v + c);
                float y1 = __ldg(g1 + c + 1) * (v[2 * j + 1] - mean) * rstd + __ldg(b1v + c + 1);
                unsigned hi, lo;
                split_pack(y0, y1, hi, lo);
                H1H[r * 68 + q * 16 + j] = hi;
                H1L[r * 68 + q * 16 + j] = lo;
            }
        } else {
            int r2 = t >> 2, q2 = t & 3;
#pragma unroll
            for (int j = 0; j < 16; j++) {
                H1H[r2 * 68 + q2 * 16 + j] = 0u;
                H1L[r2 * 68 + q2 * 16 + j] = 0u;
            }
        }
    }
    __syncthreads();

    // ---- Phase B: GEMM 64x128x128 ----
    const int n0 = w * 16;
    // ldmatrix lane geometry
    const int lrow = (lane & 7) + ((lane >> 3 & 1) << 3);   // row within 16-row tile
    const int lkw  = (lane >> 4) << 2;                      // word offset 0 or 4
    unsigned baseH[4], baseL[4];
#pragma unroll
    for (int mt = 0; mt < 4; mt++) {
        baseH[mt] = smem_u32(&H1H[(mt * 16 + lrow) * 68 + lkw]);
        baseL[mt] = smem_u32(&H1L[(mt * 16 + lrow) * 68 + lkw]);
    }

    float acc[4][2][4];
#pragma unroll
    for (int a = 0; a < 4; a++)
#pragma unroll
        for (int b = 0; b < 2; b++)
#pragma unroll
            for (int c = 0; c < 4; c++) acc[a][b][c] = 0.f;

    for (int ks = 0; ks < 8; ks++) {
        unsigned ah[4][4], al[4][4];
#pragma unroll
        for (int mt = 0; mt < 4; mt++) {
            ldsm_x4(ah[mt], baseH[mt] + ks * 32);
            ldsm_x4(al[mt], baseL[mt] + ks * 32);
        }
#pragma unroll
        for (int nt = 0; nt < 2; nt++) {
            uint4 b = __ldg(&g_wAp[(ks * 4 + q4) * D_MODEL + n0 + nt * 8 + g4]);
#pragma unroll
            for (int mt = 0; mt < 4; mt++) mma16816(acc[mt][nt], ah[mt], b.x, b.y);
#pragma unroll
            for (int mt = 0; mt < 4; mt++) mma16816(acc[mt][nt], ah[mt], b.z, b.w);
#pragma unroll
            for (int mt = 0; mt < 4; mt++) mma16816(acc[mt][nt], al[mt], b.x, b.y);
        }
    }
    __syncthreads();   // all H1 reads done; XS may overwrite

    // ---- stage result in XS [64][132] ----
#pragma unroll
    for (int nt = 0; nt < 2; nt++) {
        int c = n0 + nt * 8 + q4 * 2;
#pragma unroll
        for (int mt = 0; mt < 4; mt++) {
            int r1 = mt * 16 + g4, r2 = r1 + 8;
            XS[r1 * 132 + c]     = acc[mt][nt][0];
            XS[r1 * 132 + c + 1] = acc[mt][nt][1];
            XS[r2 * 132 + c]     = acc[mt][nt][2];
            XS[r2 * 132 + c + 1] = acc[mt][nt][3];
        }
    }
    __syncthreads();

    // ---- write g_x (coalesced) ----
    for (int idx = t; idx < 64 * 32; idx += 256) {
        int row = idx >> 5, c4 = idx & 31;
        if (row < valid)
            *(float4*)(g_x + (size_t)(row0 + row) * D_MODEL + c4 * 4) =
                *(float4*)&XS[row * 132 + c4 * 4];
    }

    // ---- attention logits: warp w handles rows w*8..w*8+7 ----
    {
        int row = w * 8 + (lane >> 2);
        int h0 = q4 * 2;
        if (row < valid) {
            float ps0 = 0.f, pd0 = 0.f, ps1 = 0.f, pd1 = 0.f;
#pragma unroll
            for (int j = 0; j < 16; j++) {
                float x0 = XS[row * 132 + h0 * 16 + j];
                float x1 = XS[row * 132 + (h0 + 1) * 16 + j];
                ps0 += x0 * __ldg(asrc + h0 * DH + j);
                pd0 += x0 * __ldg(adst + h0 * DH + j);
                ps1 += x1 * __ldg(asrc + (h0 + 1) * DH + j);
                pd1 += x1 * __ldg(adst + (h0 + 1) * DH + j);
            }
            int grow = row0 + row;
            g_as[grow * 8 + h0] = ps0;     g_ad[grow * 8 + h0] = pd0;
            g_as[grow * 8 + h0 + 1] = ps1; g_ad[grow * 8 + h0 + 1] = pd1;
        }
    }
}

// ---------------- K3: softmax denominators (no max shift) ----------
__global__ void __launch_bounds__(256) k3_den(const int* __restrict__ ei) {
    int e = blockIdx.x * 256 + threadIdx.x;
    if (e >= TOT_EDGES) return;
    int src, dst;
    if (e < E_EDGES) { src = __ldg(ei + e); dst = __ldg(ei + E_EDGES + e); }
    else             { src = dst = e - E_EDGES; }
    float4 s0 = *(const float4*)(g_as + src * 8);
    float4 s1 = *(const float4*)(g_as + src * 8 + 4);
    float4 d0 = *(const float4*)(g_ad + dst * 8);
    float4 d1 = *(const float4*)(g_ad + dst * 8 + 4);
    float4 v0 = make_float4(expf(leaky(s0.x + d0.x)), expf(leaky(s0.y + d0.y)),
                            expf(leaky(s0.z + d0.z)), expf(leaky(s0.w + d0.w)));
    float4 v1 = make_float4(expf(leaky(s1.x + d1.x)), expf(leaky(s1.y + d1.y)),
                            expf(leaky(s1.z + d1.z)), expf(leaky(s1.w + d1.w)));
    atomicAdd((float4*)(g_den + dst * 8), v0);
    atomicAdd((float4*)(g_den + dst * 8 + 4), v1);
}

// ---------------- K3b: invert denominators in place ----------------
__global__ void __launch_bounds__(256) k3b_rcp() {
    int i = blockIdx.x * 256 + threadIdx.x;
    if (i < N_NODES * H_HEADS) g_den[i] = 1.f / (g_den[i] + 1e-16f);
}

// ---------------- K4: weighted scatter (warp per edge) ------------
__global__ void __launch_bounds__(256) k4_scatter(const int* __restrict__ ei,
                                                  float* __restrict__ out) {
    int gt = blockIdx.x * 256 + threadIdx.x;
    int w = gt >> 5, l = gt & 31;
    if (w >= TOT_EDGES) return;
    int src, dst;
    if (w < E_EDGES) { src = __ldg(ei + w); dst = __ldg(ei + E_EDGES + w); }
    else             { src = dst = w - E_EDGES; }
    int h = l >> 2;
    float e = __ldg(g_as + src * 8 + h) + __ldg(g_ad + dst * 8 + h);
    float alpha = expf(leaky(e)) * __ldg(g_den + dst * 8 + h);
    float4 xv = *(const float4*)(g_x + (size_t)src * D_MODEL + l * 4);
    float4 mv = make_float4(xv.x * alpha, xv.y * alpha, xv.z * alpha, xv.w * alpha);
    atomicAdd((float4*)(out + (size_t)dst * D_MODEL + l * 4), mv);
}

// ---------------- K5: fused LN2 + FFN + residual (bf16-split MMA) ---
#define SM_H2H  0
#define SM_H2L  4352
#define SM_ACTH 8704
#define SM_ACTL 25344
#define SM_WORDS 41984   // * 4B = 167,936 bytes

__global__ void __launch_bounds__(256) k5_ffn(float* __restrict__ out,
                                              const float* __restrict__ g2,
                                              const float* __restrict__ b2v,
                                              const float* __restrict__ bb1,
                                              const float* __restrict__ bb2) {
    extern __shared__ unsigned sm[];
    unsigned* H2H = sm + SM_H2H;
    unsigned* H2L = sm + SM_H2L;
    unsigned* ACTH = sm + SM_ACTH;
    unsigned* ACTL = sm + SM_ACTL;

    const int t = threadIdx.x;
    const int lane = t & 31, w = t >> 5;
    const int g4 = lane >> 2, q4 = lane & 3;
    const int row0 = blockIdx.x * 64;
    const int valid = min(64, N_NODES - row0);

    // ldmatrix lane geometry
    const int lrow = (lane & 7) + ((lane >> 3 & 1) << 3);
    const int lkw  = (lane >> 4) << 2;

    // ---- Phase A: LN2, split to bf16 hi/lo, pack k-pairs ----
    {
        int r = t >> 2, q = t & 3;
        if (r < valid) {
            int grow = row0 + r;
            const float4* rp = (const float4*)(out + (size_t)grow * D_MODEL + q * 32);
            float v[32];
#pragma unroll
            for (int j = 0; j < 8; j++) {
                float4 x = rp[j];
                v[4 * j] = x.x; v[4 * j + 1] = x.y; v[4 * j + 2] = x.z; v[4 * j + 3] = x.w;
            }
            float s = 0.f, s2 = 0.f;
#pragma unroll
            for (int j = 0; j < 32; j++) { s += v[j]; s2 += v[j] * v[j]; }
            s  += __shfl_xor_sync(0xffffffffu, s, 1);
            s  += __shfl_xor_sync(0xffffffffu, s, 2);
            s2 += __shfl_xor_sync(0xffffffffu, s2, 1);
            s2 += __shfl_xor_sync(0xffffffffu, s2, 2);
            float mean = s * (1.f / 128.f);
            float var = (s2 * (1.f / 128.f) - mean * mean) * (128.f / 127.f);
            float rstd = 1.f / (sqrtf(fmaxf(var, 0.f)) + LN_EPS);
#pragma unroll
            for (int j = 0; j < 16; j++) {
                int c = q * 32 + 2 * j;
                float y0 = __ldg(g2 + c)     * (v[2 * j]     - mean) * rstd + __ldg(b2v + c);
                float y1 = __ldg(g2 + c + 1) * (v[2 * j + 1] - mean) * rstd + __ldg(b2v + c + 1);
                unsigned hi, lo;
                split_pack(y0, y1, hi, lo);
                H2H[r * 68 + q * 16 + j] = hi;
                H2L[r * 68 + q * 16 + j] = lo;
            }
        } else {
#pragma unroll
            for (int j = 0; j < 16; j++) {
                H2H[r * 68 + q * 16 + j] = 0u;
                H2L[r * 68 + q * 16 + j] = 0u;
            }
        }
    }
    __syncthreads();

    // ---- Phase B: GEMM1 64x512x128 + bias + relu -> ACT (2 n-chunks) ----
    {
        unsigned baseH[4], baseL[4];
#pragma unroll
        for (int mt = 0; mt < 4; mt++) {
            baseH[mt] = smem_u32(&H2H[(mt * 16 + lrow) * 68 + lkw]);
            baseL[mt] = smem_u32(&H2L[(mt * 16 + lrow) * 68 + lkw]);
        }
        for (int ch = 0; ch < 2; ch++) {
            const int n0 = w * 64 + ch * 32;
            float acc[4][4][4];
#pragma unroll
            for (int a = 0; a < 4; a++)
#pragma unroll
                for (int b = 0; b < 4; b++)
#pragma unroll
                    for (int c = 0; c < 4; c++) acc[a][b][c] = 0.f;

            for (int ks = 0; ks < 8; ks++) {
                unsigned ah[4][4], al[4][4];
#pragma unroll
                for (int mt = 0; mt < 4; mt++) {
                    ldsm_x4(ah[mt], baseH[mt] + ks * 32);
                    ldsm_x4(al[mt], baseL[mt] + ks * 32);
                }
#pragma unroll
                for (int nt = 0; nt < 4; nt++) {
                    uint4 b = __ldg(&g_w1p[(ks * 4 + q4) * DFF + n0 + nt * 8 + g4]);
#pragma unroll
                    for (int mt = 0; mt < 4; mt++) mma16816(acc[mt][nt], ah[mt], b.x, b.y);
#pragma unroll
                    for (int mt = 0; mt < 4; mt++) mma16816(acc[mt][nt], ah[mt], b.z, b.w);
#pragma unroll
                    for (int mt = 0; mt < 4; mt++) mma16816(acc[mt][nt], al[mt], b.x, b.y);
                }
            }
#pragma unroll
            for (int nt = 0; nt < 4; nt++) {
                int c = n0 + nt * 8 + q4 * 2;
                float bi0 = __ldg(bb1 + c), bi1 = __ldg(bb1 + c + 1);
                int cp = c >> 1;
#pragma unroll
                for (int mt = 0; mt < 4; mt++) {
                    int r1 = mt * 16 + g4, r2 = r1 + 8;
                    unsigned hi, lo;
                    split_pack(fmaxf(acc[mt][nt][0] + bi0, 0.f),
                               fmaxf(acc[mt][nt][1] + bi1, 0.f), hi, lo);
                    ACTH[r1 * 260 + cp] = hi; ACTL[r1 * 260 + cp] = lo;
                    split_pack(fmaxf(acc[mt][nt][2] + bi0, 0.f),
                               fmaxf(acc[mt][nt][3] + bi1, 0.f), hi, lo);
                    ACTH[r2 * 260 + cp] = hi; ACTL[r2 * 260 + cp] = lo;
                }
            }
        }
    }
    __syncthreads();

    // ---- Phase C: GEMM2 64x128x512 + bias + residual ----
    {
        unsigned baseH[4], baseL[4];
#pragma unroll
        for (int mt = 0; mt < 4; mt++) {
            baseH[mt] = smem_u32(&ACTH[(mt * 16 + lrow) * 260 + lkw]);
            baseL[mt] = smem_u32(&ACTL[(mt * 16 + lrow) * 260 + lkw]);
        }
        const int n0 = w * 16;
        float acc[4][2][4];
#pragma unroll
        for (int a = 0; a < 4; a++)
#pragma unroll
            for (int b = 0; b < 2; b++)
#pragma unroll
                for (int c = 0; c < 4; c++) acc[a][b][c] = 0.f;

        for (int ks = 0; ks < 32; ks++) {
            unsigned ah[4][4], al[4][4];
#pragma unroll
            for (int mt = 0; mt < 4; mt++) {
                ldsm_x4(ah[mt], baseH[mt] + ks * 32);
                ldsm_x4(al[mt], baseL[mt] + ks * 32);
            }
#pragma unroll
            for (int nt = 0; nt < 2; nt++) {
                uint4 b = __ldg(&g_w2p[(ks * 4 + q4) * D_MODEL + n0 + nt * 8 + g4]);
#pragma unroll
                for (int mt = 0; mt < 4; mt++) mma16816(acc[mt][nt], ah[mt], b.x, b.y);
#pragma unroll
                for (int mt = 0; mt < 4; mt++) mma16816(acc[mt][nt], ah[mt], b.z, b.w);
#pragma unroll
                for (int mt = 0; mt < 4; mt++) mma16816(acc[mt][nt], al[mt], b.x, b.y);
            }
        }
#pragma unroll
        for (int nt = 0; nt < 2; nt++) {
            int c = n0 + nt * 8 + q4 * 2;
            float bi0 = __ldg(bb2 + c), bi1 = __ldg(bb2 + c + 1);
#pragma unroll
            for (int mt = 0; mt < 4; mt++) {
                int lr1 = mt * 16 + g4, lr2 = lr1 + 8;
                if (lr1 < valid) {
                    float* p = out + (size_t)(row0 + lr1) * D_MODEL + c;
                    float2 o = *(float2*)p;
                    o.x += acc[mt][nt][0] + bi0;
                    o.y += acc[mt][nt][1] + bi1;
                    *(float2*)p = o;
                }
                if (lr2 < valid) {
                    float* p = out + (size_t)(row0 + lr2) * D_MODEL + c;
                    float2 o = *(float2*)p;
                    o.x += acc[mt][nt][2] + bi0;
                    o.y += acc[mt][nt][3] + bi1;
                    *(float2*)p = o;
                }
            }
        }
    }
}

// ---------------- host launcher -----------------------------------
extern "C" void kernel_launch(void* const* d_in, const int* in_sizes, int n_in,
                              void* d_out, int out_size) {
    const float* nf       = (const float*)d_in[0];
    const int*   ei       = (const int*)d_in[1];     // JAX demotes int64 -> int32
    const float* ln1_g    = (const float*)d_in[2];
    const float* ln1_b    = (const float*)d_in[3];
    const float* W_att    = (const float*)d_in[4];
    const float* att_src  = (const float*)d_in[5];
    const float* att_dst  = (const float*)d_in[6];
    const float* bias_att = (const float*)d_in[7];
    const float* ln2_g    = (const float*)d_in[8];
    const float* ln2_b    = (const float*)d_in[9];
    const float* W1       = (const float*)d_in[10];
    const float* b1       = (const float*)d_in[11];
    const float* W2       = (const float*)d_in[12];
    const float* b2       = (const float*)d_in[13];
    float* out = (float*)d_out;

    static int smem_set = 0;
    if (!smem_set) {
        cudaFuncSetAttribute(k5_ffn, cudaFuncAttributeMaxDynamicSharedMemorySize,
                             SM_WORDS * 4);
        smem_set = 1;
    }

    // weight split + pack: 36864 entries = 144 blocks
    kprep<<<144, 256>>>(W1, W2, W_att);
    // K1: out=nf+bias, LN1 + projection (MMA) + attention logits + den clear
    k1_ln_proj<<<(N_NODES + 63) / 64, 256, 8704 * 4>>>(nf, ln1_g, ln1_b, bias_att,
                                                       att_src, att_dst, out);
    // K3: softmax denominators
    k3_den<<<(TOT_EDGES + 255) / 256, 256>>>(ei);
    // K3b: reciprocal
    k3b_rcp<<<(N_NODES * H_HEADS + 255) / 256, 256>>>();
    // K4: weighted message scatter (one warp per edge)
    k4_scatter<<<((size_t)TOT_EDGES * 32 + 255) / 256, 256>>>(ei, out);
    // K5: fused LN2 + FFN + residual on tensor cores
    k5_ffn<<<(N_NODES + 63) / 64, 256, SM_WORDS * 4>>>(out, ln2_g, ln2_b, b1, b2);
}

// round 6
// speedup vs baseline: 2.6333x; 1.1505x over previous
#include <cuda_runtime.h>
#include <cuda_bf16.h>
#include <math.h>

#define N_NODES 50000
#define D_MODEL 128
#define H_HEADS 8
#define DH 16
#define DFF 512
#define E_EDGES 800000
#define LN_EPS 1e-6f
#define NEG_SLOPE 0.2f
#define SCAN_B 196           // 196*256 = 50176 >= N_NODES+1

// ---------------- scratch (no allocations allowed) ----------------
__device__ __align__(16) float g_x[(size_t)N_NODES * D_MODEL];   // projected features [N,128]
__device__ __align__(16) float g_as[N_NODES * H_HEADS];          // alpha_src logits
__device__ __align__(16) float g_ad[N_NODES * H_HEADS];          // alpha_dst logits
// CSR-by-dst build
__device__ __align__(16) unsigned g_cnt[SCAN_B * 256];           // histogram (zero-padded)
__device__ __align__(16) unsigned g_off[N_NODES + 1];            // segment offsets
__device__ __align__(16) unsigned g_cur[N_NODES];                // scatter cursors
__device__ __align__(16) unsigned g_bsum[256];                   // block sums
__device__ __align__(16) unsigned g_boff[256];                   // block offsets
__device__ __align__(16) int      g_srcs[E_EDGES];               // src ids sorted by dst
// packed split-bf16 weights: uint4 = (hi[kh], hi[kh+4], lo[kh], lo[kh+4])
__device__ __align__(16) uint4 g_w1p[32 * DFF];                  // W1 (k=128 -> 32 khIdx)
__device__ __align__(16) uint4 g_w2p[128 * D_MODEL];             // W2 (k=512 -> 128 khIdx)
__device__ __align__(16) uint4 g_wAp[32 * D_MODEL];              // W_att

__device__ __forceinline__ float leaky(float x) { return x > 0.f ? x : NEG_SLOPE * x; }

__device__ __forceinline__ void split_pack(float x0, float x1, unsigned& hi, unsigned& lo) {
    __nv_bfloat162 h = __floats2bfloat162_rn(x0, x1);
    float2 hf = __bfloat1622float2(h);
    __nv_bfloat162 l = __floats2bfloat162_rn(x0 - hf.x, x1 - hf.y);
    hi = *reinterpret_cast<unsigned*>(&h);
    lo = *reinterpret_cast<unsigned*>(&l);
}

__device__ __forceinline__ void mma16816(float* c, const unsigned* a, unsigned b0, unsigned b1) {
    asm volatile(
        "mma.sync.aligned.m16n8k16.row.col.f32.bf16.bf16.f32 "
        "{%0,%1,%2,%3}, {%4,%5,%6,%7}, {%8,%9}, {%0,%1,%2,%3};"
        : "+f"(c[0]), "+f"(c[1]), "+f"(c[2]), "+f"(c[3])
        : "r"(a[0]), "r"(a[1]), "r"(a[2]), "r"(a[3]), "r"(b0), "r"(b1));
}

__device__ __forceinline__ void ldsm_x4(unsigned* r, unsigned addr) {
    asm volatile("ldmatrix.sync.aligned.m8n8.x4.shared.b16 {%0,%1,%2,%3}, [%4];"
        : "=r"(r[0]), "=r"(r[1]), "=r"(r[2]), "=r"(r[3]) : "r"(addr));
}

__device__ __forceinline__ unsigned smem_u32(const void* p) {
    return (unsigned)__cvta_generic_to_shared(p);
}

// ---------------- Kprep: split + pack weights ----------------------
__global__ void __launch_bounds__(256) kprep(const float* __restrict__ W1,
                                             const float* __restrict__ W2,
                                             const float* __restrict__ WA) {
    int i = blockIdx.x * 256 + threadIdx.x;
    const float* W; int cols, idx; uint4* dst;
    if (i < 32 * DFF)                       { W = W1; cols = DFF;     idx = i;                       dst = g_w1p; }
    else if (i < 32 * DFF + 128 * D_MODEL)  { W = W2; cols = D_MODEL; idx = i - 32 * DFF;            dst = g_w2p; }
    else                                    { W = WA; cols = D_MODEL; idx = i - 32 * DFF - 128 * D_MODEL; dst = g_wAp; }
    int khi = idx / cols, n = idx % cols;
    int ks = khi >> 2, q = khi & 3;
    int kh = ks * 8 + q;
    unsigned h0, l0, h1, l1;
    split_pack(W[(2 * kh) * cols + n],     W[(2 * kh + 1) * cols + n], h0, l0);
    split_pack(W[(2 * kh + 8) * cols + n], W[(2 * kh + 9) * cols + n], h1, l1);
    dst[idx] = make_uint4(h0, h1, l0, l1);
}

// ---------------- CSR build ----------------------------------------
__global__ void __launch_bounds__(256) kz() {
    g_cnt[blockIdx.x * 256 + threadIdx.x] = 0u;   // grid = SCAN_B
}
__global__ void __launch_bounds__(256) ks_hist(const int* __restrict__ ei) {
    int e = blockIdx.x * 256 + threadIdx.x;
    if (e < E_EDGES) atomicAdd(&g_cnt[__ldg(ei + E_EDGES + e)], 1u);
}
__global__ void __launch_bounds__(256) ks_scan1() {
    __shared__ unsigned s[256];
    int t = threadIdx.x;
    s[t] = g_cnt[blockIdx.x * 256 + t];
    __syncthreads();
#pragma unroll
    for (int o = 128; o; o >>= 1) {
        if (t < o) s[t] += s[t + o];
        __syncthreads();
    }
    if (t == 0) g_bsum[blockIdx.x] = s[0];
}
__global__ void __launch_bounds__(256) ks_scan2() {
    __shared__ unsigned s[256];
    int t = threadIdx.x;
    unsigned v = (t < SCAN_B) ? g_bsum[t] : 0u;
    s[t] = v;
    __syncthreads();
#pragma unroll
    for (int o = 1; o < 256; o <<= 1) {
        unsigned add = (t >= o) ? s[t - o] : 0u;
        __syncthreads();
        s[t] += add;
        __syncthreads();
    }
    if (t < SCAN_B) g_boff[t] = s[t] - v;      // exclusive
}
__global__ void __launch_bounds__(256) ks_scan3() {
    __shared__ unsigned s[256];
    int t = threadIdx.x;
    int i = blockIdx.x * 256 + t;
    unsigned v = g_cnt[i];
    s[t] = v;
    __syncthreads();
#pragma unroll
    for (int o = 1; o < 256; o <<= 1) {
        unsigned add = (t >= o) ? s[t - o] : 0u;
        __syncthreads();
        s[t] += add;
        __syncthreads();
    }
    unsigned excl = s[t] - v + g_boff[blockIdx.x];
    if (i <= N_NODES) g_off[i] = excl;
    if (i < N_NODES)  g_cur[i] = excl;
}
__global__ void __launch_bounds__(256) ks_scat(const int* __restrict__ ei) {
    int e = blockIdx.x * 256 + threadIdx.x;
    if (e >= E_EDGES) return;
    int src = __ldg(ei + e), dst = __ldg(ei + E_EDGES + e);
    unsigned p = atomicAdd(&g_cur[dst], 1u);
    g_srcs[p] = src;
}

// ---------------- K1: LN1 -> x = h1 @ W_att (MMA); a_s, a_d; out=nf+bias
__global__ void __launch_bounds__(256) k1_ln_proj(const float* __restrict__ nf,
                                                  const float* __restrict__ g1,
                                                  const float* __restrict__ b1v,
                                                  const float* __restrict__ bias_att,
                                                  const float* __restrict__ asrc,
                                                  const float* __restrict__ adst,
                                                  float* __restrict__ out) {
    extern __shared__ unsigned sm[];
    unsigned* H1H = sm;
    unsigned* H1L = sm + 4352;
    float* XS = (float*)sm;              // aliases H1 after phase B

    const int t = threadIdx.x;
    const int lane = t & 31, w = t >> 5;
    const int g4 = lane >> 2, q4 = lane & 3;
    const int row0 = blockIdx.x * 64;
    const int valid = min(64, N_NODES - row0);

    // ---- Phase A: LN1, out = nf + bias_att, split to bf16 hi/lo ----
    {
        int r = t >> 2, q = t & 3;
        if (r < valid) {
            int grow = row0 + r;
            const float4* rp = (const float4*)(nf + (size_t)grow * D_MODEL + q * 32);
            float v[32];
#pragma unroll
            for (int j = 0; j < 8; j++) {
                float4 x = rp[j];
                v[4 * j] = x.x; v[4 * j + 1] = x.y; v[4 * j + 2] = x.z; v[4 * j + 3] = x.w;
            }
            float4* op = (float4*)(out + (size_t)grow * D_MODEL + q * 32);
#pragma unroll
            for (int j = 0; j < 8; j++) {
                int c = q * 32 + 4 * j;
                op[j] = make_float4(v[4 * j]     + __ldg(bias_att + c),
                                    v[4 * j + 1] + __ldg(bias_att + c + 1),
                                    v[4 * j + 2] + __ldg(bias_att + c + 2),
                                    v[4 * j + 3] + __ldg(bias_att + c + 3));
            }
            float s = 0.f, s2 = 0.f;
#pragma unroll
            for (int j = 0; j < 32; j++) { s += v[j]; s2 += v[j] * v[j]; }
            s  += __shfl_xor_sync(0xffffffffu, s, 1);
            s  += __shfl_xor_sync(0xffffffffu, s, 2);
            s2 += __shfl_xor_sync(0xffffffffu, s2, 1);
            s2 += __shfl_xor_sync(0xffffffffu, s2, 2);
            float mean = s * (1.f / 128.f);
            float var = (s2 * (1.f / 128.f) - mean * mean) * (128.f / 127.f);
            float rstd = 1.f / (sqrtf(fmaxf(var, 0.f)) + LN_EPS);
#pragma unroll
            for (int j = 0; j < 16; j++) {
                int c = q * 32 + 2 * j;
                float y0 = __ldg(g1 + c)     * (v[2 * j]     - mean) * rstd + __ldg(b1v + c);
                float y1 = __ldg(g1 + c + 1) * (v[2 * j + 1] - mean) * rstd + __ldg(b1v + c + 1);
                unsigned hi, lo;
                split_pack(y0, y1, hi, lo);
                H1H[r * 68 + q * 16 + j] = hi;
                H1L[r * 68 + q * 16 + j] = lo;
            }
        } else {
            int r2 = t >> 2, q2 = t & 3;
#pragma unroll
            for (int j = 0; j < 16; j++) {
                H1H[r2 * 68 + q2 * 16 + j] = 0u;
                H1L[r2 * 68 + q2 * 16 + j] = 0u;
            }
        }
    }
    __syncthreads();

    // ---- Phase B: GEMM 64x128x128 ----
    const int n0 = w * 16;
    const int lrow = (lane & 7) + ((lane >> 3 & 1) << 3);
    const int lkw  = (lane >> 4) << 2;
    unsigned baseH[4], baseL[4];
#pragma unroll
    for (int mt = 0; mt < 4; mt++) {
        baseH[mt] = smem_u32(&H1H[(mt * 16 + lrow) * 68 + lkw]);
        baseL[mt] = smem_u32(&H1L[(mt * 16 + lrow) * 68 + lkw]);
    }

    float acc[4][2][4];
#pragma unroll
    for (int a = 0; a < 4; a++)
#pragma unroll
        for (int b = 0; b < 2; b++)
#pragma unroll
            for (int c = 0; c < 4; c++) acc[a][b][c] = 0.f;

    for (int ks = 0; ks < 8; ks++) {
        unsigned ah[4][4], al[4][4];
#pragma unroll
        for (int mt = 0; mt < 4; mt++) {
            ldsm_x4(ah[mt], baseH[mt] + ks * 32);
            ldsm_x4(al[mt], baseL[mt] + ks * 32);
        }
#pragma unroll
        for (int nt = 0; nt < 2; nt++) {
            uint4 b = __ldg(&g_wAp[(ks * 4 + q4) * D_MODEL + n0 + nt * 8 + g4]);
#pragma unroll
            for (int mt = 0; mt < 4; mt++) mma16816(acc[mt][nt], ah[mt], b.x, b.y);
#pragma unroll
            for (int mt = 0; mt < 4; mt++) mma16816(acc[mt][nt], ah[mt], b.z, b.w);
#pragma unroll
            for (int mt = 0; mt < 4; mt++) mma16816(acc[mt][nt], al[mt], b.x, b.y);
        }
    }
    __syncthreads();

    // ---- stage result in XS [64][132] ----
#pragma unroll
    for (int nt = 0; nt < 2; nt++) {
        int c = n0 + nt * 8 + q4 * 2;
#pragma unroll
        for (int mt = 0; mt < 4; mt++) {
            int r1 = mt * 16 + g4, r2 = r1 + 8;
            XS[r1 * 132 + c]     = acc[mt][nt][0];
            XS[r1 * 132 + c + 1] = acc[mt][nt][1];
            XS[r2 * 132 + c]     = acc[mt][nt][2];
            XS[r2 * 132 + c + 1] = acc[mt][nt][3];
        }
    }
    __syncthreads();

    // ---- write g_x (coalesced) ----
    for (int idx = t; idx < 64 * 32; idx += 256) {
        int row = idx >> 5, c4 = idx & 31;
        if (row < valid)
            *(float4*)(g_x + (size_t)(row0 + row) * D_MODEL + c4 * 4) =
                *(float4*)&XS[row * 132 + c4 * 4];
    }

    // ---- attention logits ----
    {
        int row = w * 8 + (lane >> 2);
        int h0 = q4 * 2;
        if (row < valid) {
            float ps0 = 0.f, pd0 = 0.f, ps1 = 0.f, pd1 = 0.f;
#pragma unroll
            for (int j = 0; j < 16; j++) {
                float x0 = XS[row * 132 + h0 * 16 + j];
                float x1 = XS[row * 132 + (h0 + 1) * 16 + j];
                ps0 += x0 * __ldg(asrc + h0 * DH + j);
                pd0 += x0 * __ldg(adst + h0 * DH + j);
                ps1 += x1 * __ldg(asrc + (h0 + 1) * DH + j);
                pd1 += x1 * __ldg(adst + (h0 + 1) * DH + j);
            }
            int grow = row0 + row;
            g_as[grow * 8 + h0] = ps0;     g_ad[grow * 8 + h0] = pd0;
            g_as[grow * 8 + h0 + 1] = ps1; g_ad[grow * 8 + h0 + 1] = pd1;
        }
    }
}

// ---------------- K4: gather attention (warp per dst node) ---------
__global__ void __launch_bounds__(256) k4_gather(float* __restrict__ out) {
    int wid = (blockIdx.x * 256 + threadIdx.x) >> 5;
    int lane = threadIdx.x & 31;
    if (wid >= N_NODES) return;
    const int dst = wid;
    const int start = g_off[dst], end = g_off[dst + 1];

    // ---- pass 1: softmax denominators for all 8 heads ----
    const int h8 = lane & 7;
    const float ad8 = g_as == g_as ? g_ad[dst * 8 + h8] : 0.f;   // dst logit, head h8
    const float es_self = expf(leaky(g_as[dst * 8 + h8] + ad8)); // self-loop term
    float den = 0.f;
    for (int base = start; base < end; base += 4) {
        int eidx = base + (lane >> 3);
        if (eidx < end) {
            int src = __ldg(&g_srcs[eidx]);
            den += expf(leaky(__ldg(&g_as[src * 8 + h8]) + ad8));
        }
    }
    den += __shfl_xor_sync(0xffffffffu, den, 8);
    den += __shfl_xor_sync(0xffffffffu, den, 16);
    den += es_self;
    const float rden = 1.f / (den + 1e-16f);

    // ---- pass 2: weighted accumulate, lane owns cols lane*4..lane*4+3 ----
    const int hc = lane >> 2;
    const float rden_h = __shfl_sync(0xffffffffu, rden, hc);
    const float a_self = __shfl_sync(0xffffffffu, es_self, hc) * rden_h;
    const float adv    = __shfl_sync(0xffffffffu, ad8, hc);

    float4 xd = *(const float4*)(g_x + (size_t)dst * D_MODEL + lane * 4);
    float4 acc = make_float4(a_self * xd.x, a_self * xd.y, a_self * xd.z, a_self * xd.w);
    for (int e = start; e < end; e++) {
        int src = __ldg(&g_srcs[e]);
        float a = expf(leaky(__ldg(&g_as[src * 8 + hc]) + adv)) * rden_h;
        float4 xv = *(const float4*)(g_x + (size_t)src * D_MODEL + lane * 4);
        acc.x += a * xv.x; acc.y += a * xv.y; acc.z += a * xv.z; acc.w += a * xv.w;
    }
    float4* p = (float4*)(out + (size_t)dst * D_MODEL + lane * 4);
    float4 o = *p;
    o.x += acc.x; o.y += acc.y; o.z += acc.z; o.w += acc.w;
    *p = o;
}

// ---------------- K5: fused LN2 + FFN + residual (bf16-split MMA) ---
#define SM_H2H  0
#define SM_H2L  4352
#define SM_ACTH 8704
#define SM_ACTL 25344
#define SM_WORDS 41984   // * 4B = 167,936 bytes

__global__ void __launch_bounds__(256) k5_ffn(float* __restrict__ out,
                                              const float* __restrict__ g2,
                                              const float* __restrict__ b2v,
                                              const float* __restrict__ bb1,
                                              const float* __restrict__ bb2) {
    extern __shared__ unsigned sm[];
    unsigned* H2H = sm + SM_H2H;
    unsigned* H2L = sm + SM_H2L;
    unsigned* ACTH = sm + SM_ACTH;
    unsigned* ACTL = sm + SM_ACTL;

    const int t = threadIdx.x;
    const int lane = t & 31, w = t >> 5;
    const int g4 = lane >> 2, q4 = lane & 3;
    const int row0 = blockIdx.x * 64;
    const int valid = min(64, N_NODES - row0);

    const int lrow = (lane & 7) + ((lane >> 3 & 1) << 3);
    const int lkw  = (lane >> 4) << 2;

    // ---- Phase A: LN2 ----
    {
        int r = t >> 2, q = t & 3;
        if (r < valid) {
            int grow = row0 + r;
            const float4* rp = (const float4*)(out + (size_t)grow * D_MODEL + q * 32);
            float v[32];
#pragma unroll
            for (int j = 0; j < 8; j++) {
                float4 x = rp[j];
                v[4 * j] = x.x; v[4 * j + 1] = x.y; v[4 * j + 2] = x.z; v[4 * j + 3] = x.w;
            }
            float s = 0.f, s2 = 0.f;
#pragma unroll
            for (int j = 0; j < 32; j++) { s += v[j]; s2 += v[j] * v[j]; }
            s  += __shfl_xor_sync(0xffffffffu, s, 1);
            s  += __shfl_xor_sync(0xffffffffu, s, 2);
            s2 += __shfl_xor_sync(0xffffffffu, s2, 1);
            s2 += __shfl_xor_sync(0xffffffffu, s2, 2);
            float mean = s * (1.f / 128.f);
            float var = (s2 * (1.f / 128.f) - mean * mean) * (128.f / 127.f);
            float rstd = 1.f / (sqrtf(fmaxf(var, 0.f)) + LN_EPS);
#pragma unroll
            for (int j = 0; j < 16; j++) {
                int c = q * 32 + 2 * j;
                float y0 = __ldg(g2 + c)     * (v[2 * j]     - mean) * rstd + __ldg(b2v + c);
                float y1 = __ldg(g2 + c + 1) * (v[2 * j + 1] - mean) * rstd + __ldg(b2v + c + 1);
                unsigned hi, lo;
                split_pack(y0, y1, hi, lo);
                H2H[r * 68 + q * 16 + j] = hi;
                H2L[r * 68 + q * 16 + j] = lo;
            }
        } else {
#pragma unroll
            for (int j = 0; j < 16; j++) {
                H2H[r * 68 + q * 16 + j] = 0u;
                H2L[r * 68 + q * 16 + j] = 0u;
            }
        }
    }
    __syncthreads();

    // ---- Phase B: GEMM1 64x512x128 + bias + relu -> ACT ----
    {
        unsigned baseH[4], baseL[4];
#pragma unroll
        for (int mt = 0; mt < 4; mt++) {
            baseH[mt] = smem_u32(&H2H[(mt * 16 + lrow) * 68 + lkw]);
            baseL[mt] = smem_u32(&H2L[(mt * 16 + lrow) * 68 + lkw]);
        }
        for (int ch = 0; ch < 2; ch++) {
            const int n0 = w * 64 + ch * 32;
            float acc[4][4][4];
#pragma unroll
            for (int a = 0; a < 4; a++)
#pragma unroll
                for (int b = 0; b < 4; b++)
#pragma unroll
                    for (int c = 0; c < 4; c++) acc[a][b][c] = 0.f;

            for (int ks = 0; ks < 8; ks++) {
                unsigned ah[4][4], al[4][4];
#pragma unroll
                for (int mt = 0; mt < 4; mt++) {
                    ldsm_x4(ah[mt], baseH[mt] + ks * 32);
                    ldsm_x4(al[mt], baseL[mt] + ks * 32);
                }
#pragma unroll
                for (int nt = 0; nt < 4; nt++) {
                    uint4 b = __ldg(&g_w1p[(ks * 4 + q4) * DFF + n0 + nt * 8 + g4]);
#pragma unroll
                    for (int mt = 0; mt < 4; mt++) mma16816(acc[mt][nt], ah[mt], b.x, b.y);
#pragma unroll
                    for (int mt = 0; mt < 4; mt++) mma16816(acc[mt][nt], ah[mt], b.z, b.w);
#pragma unroll
                    for (int mt = 0; mt < 4; mt++) mma16816(acc[mt][nt], al[mt], b.x, b.y);
                }
            }
#pragma unroll
            for (int nt = 0; nt < 4; nt++) {
                int c = n0 + nt * 8 + q4 * 2;
                float bi0 = __ldg(bb1 + c), bi1 = __ldg(bb1 + c + 1);
                int cp = c >> 1;
#pragma unroll
                for (int mt = 0; mt < 4; mt++) {
                    int r1 = mt * 16 + g4, r2 = r1 + 8;
                    unsigned hi, lo;
                    split_pack(fmaxf(acc[mt][nt][0] + bi0, 0.f),
                               fmaxf(acc[mt][nt][1] + bi1, 0.f), hi, lo);
                    ACTH[r1 * 260 + cp] = hi; ACTL[r1 * 260 + cp] = lo;
                    split_pack(fmaxf(acc[mt][nt][2] + bi0, 0.f),
                               fmaxf(acc[mt][nt][3] + bi1, 0.f), hi, lo);
                    ACTH[r2 * 260 + cp] = hi; ACTL[r2 * 260 + cp] = lo;
                }
            }
        }
    }
    __syncthreads();

    // ---- Phase C: GEMM2 64x128x512 + bias + residual ----
    {
        unsigned baseH[4], baseL[4];
#pragma unroll
        for (int mt = 0; mt < 4; mt++) {
            baseH[mt] = smem_u32(&ACTH[(mt * 16 + lrow) * 260 + lkw]);
            baseL[mt] = smem_u32(&ACTL[(mt * 16 + lrow) * 260 + lkw]);
        }
        const int n0 = w * 16;
        float acc[4][2][4];
#pragma unroll
        for (int a = 0; a < 4; a++)
#pragma unroll
            for (int b = 0; b < 2; b++)
#pragma unroll
                for (int c = 0; c < 4; c++) acc[a][b][c] = 0.f;

        for (int ks = 0; ks < 32; ks++) {
            unsigned ah[4][4], al[4][4];
#pragma unroll
            for (int mt = 0; mt < 4; mt++) {
                ldsm_x4(ah[mt], baseH[mt] + ks * 32);
                ldsm_x4(al[mt], baseL[mt] + ks * 32);
            }
#pragma unroll
            for (int nt = 0; nt < 2; nt++) {
                uint4 b = __ldg(&g_w2p[(ks * 4 + q4) * D_MODEL + n0 + nt * 8 + g4]);
#pragma unroll
                for (int mt = 0; mt < 4; mt++) mma16816(acc[mt][nt], ah[mt], b.x, b.y);
#pragma unroll
                for (int mt = 0; mt < 4; mt++) mma16816(acc[mt][nt], ah[mt], b.z, b.w);
#pragma unroll
                for (int mt = 0; mt < 4; mt++) mma16816(acc[mt][nt], al[mt], b.x, b.y);
            }
        }
#pragma unroll
        for (int nt = 0; nt < 2; nt++) {
            int c = n0 + nt * 8 + q4 * 2;
            float bi0 = __ldg(bb2 + c), bi1 = __ldg(bb2 + c + 1);
#pragma unroll
            for (int mt = 0; mt < 4; mt++) {
                int lr1 = mt * 16 + g4, lr2 = lr1 + 8;
                if (lr1 < valid) {
                    float* p = out + (size_t)(row0 + lr1) * D_MODEL + c;
                    float2 o = *(float2*)p;
                    o.x += acc[mt][nt][0] + bi0;
                    o.y += acc[mt][nt][1] + bi1;
                    *(float2*)p = o;
                }
                if (lr2 < valid) {
                    float* p = out + (size_t)(row0 + lr2) * D_MODEL + c;
                    float2 o = *(float2*)p;
                    o.x += acc[mt][nt][2] + bi0;
                    o.y += acc[mt][nt][3] + bi1;
                    *(float2*)p = o;
                }
            }
        }
    }
}

// ---------------- host launcher -----------------------------------
extern "C" void kernel_launch(void* const* d_in, const int* in_sizes, int n_in,
                              void* d_out, int out_size) {
    const float* nf       = (const float*)d_in[0];
    const int*   ei       = (const int*)d_in[1];     // JAX demotes int64 -> int32
    const float* ln1_g    = (const float*)d_in[2];
    const float* ln1_b    = (const float*)d_in[3];
    const float* W_att    = (const float*)d_in[4];
    const float* att_src  = (const float*)d_in[5];
    const float* att_dst  = (const float*)d_in[6];
    const float* bias_att = (const float*)d_in[7];
    const float* ln2_g    = (const float*)d_in[8];
    const float* ln2_b    = (const float*)d_in[9];
    const float* W1       = (const float*)d_in[10];
    const float* b1       = (const float*)d_in[11];
    const float* W2       = (const float*)d_in[12];
    const float* b2       = (const float*)d_in[13];
    float* out = (float*)d_out;

    static int smem_set = 0;
    if (!smem_set) {
        cudaFuncSetAttribute(k5_ffn, cudaFuncAttributeMaxDynamicSharedMemorySize,
                             SM_WORDS * 4);
        smem_set = 1;
    }

    const int egrid = (E_EDGES + 255) / 256;

    // CSR build (independent of features) + weight prep
    kz<<<SCAN_B, 256>>>();
    kprep<<<144, 256>>>(W1, W2, W_att);
    ks_hist<<<egrid, 256>>>(ei);
    ks_scan1<<<SCAN_B, 256>>>();
    ks_scan2<<<1, 256>>>();
    ks_scan3<<<SCAN_B, 256>>>();
    ks_scat<<<egrid, 256>>>(ei);
    // K1: out=nf+bias, LN1 + projection (MMA) + attention logits
    k1_ln_proj<<<(N_NODES + 63) / 64, 256, 8704 * 4>>>(nf, ln1_g, ln1_b, bias_att,
                                                       att_src, att_dst, out);
    // K4: fused softmax + gather (warp per dst), no atomics
    k4_gather<<<(N_NODES * 32 + 255) / 256, 256>>>(out);
    // K5: fused LN2 + FFN + residual on tensor cores
    k5_ffn<<<(N_NODES + 63) / 64, 256, SM_WORDS * 4>>>(out, ln2_g, ln2_b, b1, b2);
}